// round 6
// baseline (speedup 1.0000x reference)
#include <cuda_runtime.h>
#include <stdint.h>
#include <math.h>

// Problem constants
constexpr int NB = 64;    // batch
constexpr int NT = 256;   // time
constexpr int ND = 256;   // embed dim
constexpr int NH = 256;   // hidden per direction
constexpr int NC = 32;    // tags
constexpr int NG = 1024;  // 4*NH gate rows

// Scratch (static device allocations; no cudaMalloc allowed)
__device__ __align__(16) float g_gates[(size_t)2 * NB * NT * NG]; // input-projected gate preacts per dir
__device__ __align__(16) float g_h[(size_t)2 * NB * NT * NH];     // LSTM outputs per dir (bwd in reversed time)
__device__ __align__(16) float g_em[(size_t)NB * NT * NC];        // emissions
__device__ __align__(16) float g_wOutT[(size_t)2 * NH * NC];      // w_out transposed: [k][c]

__device__ __forceinline__ float sigf(float x) { return 1.0f / (1.0f + __expf(-x)); }

// Packed fp32x2 helpers (Blackwell FFMA2 path; bit-exact fp32 FMA semantics)
__device__ __forceinline__ void fma2(unsigned long long& d, unsigned long long a,
                                     unsigned long long b) {
    asm("fma.rn.f32x2 %0, %1, %2, %0;" : "+l"(d) : "l"(a), "l"(b));
}
__device__ __forceinline__ unsigned long long pk2(float x, float y) {
    unsigned long long r;
    asm("mov.b64 %0, {%1, %2};" : "=l"(r) : "r"(__float_as_uint(x)), "r"(__float_as_uint(y)));
    return r;
}
__device__ __forceinline__ float lo2(unsigned long long v) {
    return __uint_as_float((unsigned)(v & 0xffffffffull));
}
__device__ __forceinline__ float hi2(unsigned long long v) {
    return __uint_as_float((unsigned)(v >> 32));
}

// ---------------------------------------------------------------------------
// Kernel 0: transpose w_out [32][512] -> g_wOutT[512][32]
// ---------------------------------------------------------------------------
__global__ void transpose_wout_kernel(const float* __restrict__ w)
{
    __shared__ float tile[32][33];
    const int k0 = blockIdx.x * 32;
    const int tx = threadIdx.x, ty = threadIdx.y;
#pragma unroll
    for (int i = 0; i < 32; i += 8)
        tile[ty + i][tx] = w[(size_t)(ty + i) * (2 * NH) + k0 + tx];
    __syncthreads();
#pragma unroll
    for (int i = 0; i < 32; i += 8)
        g_wOutT[(size_t)(k0 + ty + i) * NC + tx] = tile[tx][ty + i];
}

// ---------------------------------------------------------------------------
// Kernel 1: embedding gather + input projection for both directions.
// SGEMM BM=128,BN=128,BK=16, 256 threads, 8x8 microtile via packed f32x2 FMA.
// ---------------------------------------------------------------------------
__global__ void __launch_bounds__(256) input_proj_kernel(
    const int* __restrict__ sent, const int* __restrict__ lens,
    const float* __restrict__ emb,
    const float* __restrict__ w_f, const float* __restrict__ bi_f, const float* __restrict__ bh_f,
    const float* __restrict__ w_b, const float* __restrict__ bi_b, const float* __restrict__ bh_b)
{
    const int dir = blockIdx.y >> 3;
    const int n0  = (blockIdx.y & 7) * 128;
    const int m0  = blockIdx.x * 128;

    const float* __restrict__ W  = dir ? w_b  : w_f;
    const float* __restrict__ BI = dir ? bi_b : bi_f;
    const float* __restrict__ BH = dir ? bh_b : bh_f;

    __shared__ __align__(16) float As[16][128];
    __shared__ __align__(16) float Bs[16][128];
    __shared__ int toks[128];

    const int tid = threadIdx.x;
    if (tid < 128) {
        int m = m0 + tid;
        int b = m >> 8, t = m & 255;
        int ts = t;
        if (dir) { int len = lens[b]; if (t < len) ts = len - 1 - t; }
        toks[tid] = sent[b * NT + ts];
    }
    __syncthreads();

    const int lrow2 = tid >> 2;   // 0..63
    const int lane4 = tid & 3;    // 0..3
    const int row0 = lrow2, row1 = lrow2 + 64;
    const float* arow0 = emb + (size_t)toks[row0] * ND + lane4 * 4;
    const float* arow1 = emb + (size_t)toks[row1] * ND + lane4 * 4;
    const float* brow0 = W + (size_t)(n0 + row0) * ND + lane4 * 4;
    const float* brow1 = W + (size_t)(n0 + row1) * ND + lane4 * 4;

    const int tx = tid & 15, ty = tid >> 4;

    unsigned long long acc2[8][4];
#pragma unroll
    for (int i = 0; i < 8; i++)
#pragma unroll
        for (int j = 0; j < 4; j++) acc2[i][j] = 0ull;

    for (int kk = 0; kk < ND; kk += 16) {
        float4 a0 = *(const float4*)(arow0 + kk);
        float4 a1 = *(const float4*)(arow1 + kk);
        float4 b0 = *(const float4*)(brow0 + kk);
        float4 b1 = *(const float4*)(brow1 + kk);
        As[lane4 * 4 + 0][row0] = a0.x; As[lane4 * 4 + 1][row0] = a0.y;
        As[lane4 * 4 + 2][row0] = a0.z; As[lane4 * 4 + 3][row0] = a0.w;
        As[lane4 * 4 + 0][row1] = a1.x; As[lane4 * 4 + 1][row1] = a1.y;
        As[lane4 * 4 + 2][row1] = a1.z; As[lane4 * 4 + 3][row1] = a1.w;
        Bs[lane4 * 4 + 0][row0] = b0.x; Bs[lane4 * 4 + 1][row0] = b0.y;
        Bs[lane4 * 4 + 2][row0] = b0.z; Bs[lane4 * 4 + 3][row0] = b0.w;
        Bs[lane4 * 4 + 0][row1] = b1.x; Bs[lane4 * 4 + 1][row1] = b1.y;
        Bs[lane4 * 4 + 2][row1] = b1.z; Bs[lane4 * 4 + 3][row1] = b1.w;
        __syncthreads();
#pragma unroll
        for (int k = 0; k < 16; ++k) {
            float4 av0 = *(const float4*)&As[k][ty * 8];
            float4 av1 = *(const float4*)&As[k][ty * 8 + 4];
            float4 bv0 = *(const float4*)&Bs[k][tx * 8];
            float4 bv1 = *(const float4*)&Bs[k][tx * 8 + 4];
            unsigned long long a2[8];
            a2[0] = pk2(av0.x, av0.x); a2[1] = pk2(av0.y, av0.y);
            a2[2] = pk2(av0.z, av0.z); a2[3] = pk2(av0.w, av0.w);
            a2[4] = pk2(av1.x, av1.x); a2[5] = pk2(av1.y, av1.y);
            a2[6] = pk2(av1.z, av1.z); a2[7] = pk2(av1.w, av1.w);
            unsigned long long b2[4];
            b2[0] = pk2(bv0.x, bv0.y); b2[1] = pk2(bv0.z, bv0.w);
            b2[2] = pk2(bv1.x, bv1.y); b2[3] = pk2(bv1.z, bv1.w);
#pragma unroll
            for (int i = 0; i < 8; i++)
#pragma unroll
                for (int j = 0; j < 4; j++) fma2(acc2[i][j], a2[i], b2[j]);
        }
        __syncthreads();
    }

    float bias[8];
#pragma unroll
    for (int j = 0; j < 8; j++) {
        int n = n0 + tx * 8 + j;
        bias[j] = BI[n] + BH[n];
    }
#pragma unroll
    for (int i = 0; i < 8; i++) {
        int m = m0 + ty * 8 + i;
        float* o = g_gates + ((size_t)dir * (NB * NT) + m) * NG + n0 + tx * 8;
        float4 s0, s1;
        s0.x = lo2(acc2[i][0]) + bias[0]; s0.y = hi2(acc2[i][0]) + bias[1];
        s0.z = lo2(acc2[i][1]) + bias[2]; s0.w = hi2(acc2[i][1]) + bias[3];
        s1.x = lo2(acc2[i][2]) + bias[4]; s1.y = hi2(acc2[i][2]) + bias[5];
        s1.z = lo2(acc2[i][3]) + bias[6]; s1.w = hi2(acc2[i][3]) + bias[7];
        *(float4*)o = s0;
        *(float4*)(o + 4) = s1;
    }
}

// ---------------------------------------------------------------------------
// Kernel 2: weight-stationary cluster LSTM.
// 128 CTAs = 16 clusters x 8. Cluster = (dir, batch-group of 8).
// CTA rank r owns h-cols [32r, 32r+32): 128 gate rows x 256 k = 128KB in SMEM.
// Per step: compute own gate slice for 8 batches, activate, exchange h chunks
// via DSMEM writes, barrier.cluster.
// ---------------------------------------------------------------------------
constexpr int LSMEM_FLOATS = 32768 /*weights*/ + 4096 /*hs dbl buf*/ + 1024 /*gs*/;
constexpr int LSMEM_BYTES = LSMEM_FLOATS * 4;

__global__ void __launch_bounds__(256, 1) __cluster_dims__(8, 1, 1)
lstm_cluster_kernel(const float* __restrict__ w_hh_f, const float* __restrict__ w_hh_b)
{
    extern __shared__ __align__(16) float smem[];
    float* sW = smem;                  // [k4][128 rows][4 k]  (32768 floats)
    float* hs = smem + 32768;          // [2][8 batches][256]  (4096 floats)
    float* gs = smem + 32768 + 4096;   // [8 batches][128 rows] (1024 floats)

    const int tid = threadIdx.x;
    uint32_t rank;
    asm("mov.u32 %0, %%cluster_ctarank;" : "=r"(rank));
    const int cl = blockIdx.x >> 3;
    const int dir = cl & 1;
    const int bgrp = cl >> 1;          // 0..7 -> batches bgrp*8 .. +8

    const float* __restrict__ whh = dir ? w_hh_b : w_hh_f;

    // ---- Preload weight slice into SMEM: row rr -> gate=rr>>5, j=32*rank+(rr&31)
    for (int idx = tid; idx < 128 * 256; idx += 256) {
        int rr = idx >> 8, k = idx & 255;
        int gate = rr >> 5;
        int g = gate * 256 + 32 * (int)rank + (rr & 31);
        sW[(k >> 2) * 512 + rr * 4 + (k & 3)] = whh[(size_t)g * NH + k];
    }
    // init h buffers (both phases)
    for (int idx = tid; idx < 4096; idx += 256) hs[idx] = 0.0f;

    // shared-address bases for DSMEM exchange
    uint32_t hs_sh;
    {
        asm("{ .reg .u64 t; cvta.to.shared.u64 t, %1; cvt.u32.u64 %0, t; }"
            : "=r"(hs_sh) : "l"(hs));
    }
    uint32_t rdst[8];
#pragma unroll
    for (int r = 0; r < 8; ++r)
        asm("mapa.shared::cluster.u32 %0, %1, %2;" : "=r"(rdst[r]) : "r"(hs_sh), "r"(r));

    // gate-compute mapping: warp w: row-group rg=w&3, batch-group bg=w>>2
    const int w = tid >> 5, l = tid & 31;
    const int rg = w & 3, bg = w >> 2;
    const int rr = rg * 32 + l;               // 0..127 ; gate = rg
    const int grow = rg * 256 + 32 * (int)rank + l;
    const float4* sW4 = (const float4*)sW;    // sW4[k4*128 + rr]

    const float* gin[4];
#pragma unroll
    for (int i = 0; i < 4; ++i)
        gin[i] = g_gates + ((size_t)(dir * NB + bgrp * 8 + bg * 4 + i)) * NT * NG + grow;

    // activation mapping: b = tid>>5, j = tid&31 ; cell state in register
    const int ab = tid >> 5, aj = tid & 31;
    float c_reg = 0.0f;
    float* ghout = g_h + ((size_t)(dir * NB + bgrp * 8 + ab)) * (NT * NH) + 32 * (int)rank + aj;

    // all CTAs: weights + h init visible cluster-wide before first exchange
    asm volatile("barrier.cluster.arrive.aligned;" ::: "memory");
    asm volatile("barrier.cluster.wait.aligned;" ::: "memory");

    for (int t = 0; t < NT; ++t) {
        const int cur = t & 1, nxt = cur ^ 1;
        // issue gin loads early (consumed after k-loop)
        float gi0 = gin[0][(size_t)t * NG];
        float gi1 = gin[1][(size_t)t * NG];
        float gi2 = gin[2][(size_t)t * NG];
        float gi3 = gin[3][(size_t)t * NG];

        float acc0 = 0.f, acc1 = 0.f, acc2v = 0.f, acc3 = 0.f;
        if (t > 0) {
            const float4* h0 = (const float4*)(hs + cur * 2048 + (bg * 4 + 0) * 256);
            const float4* h1 = (const float4*)(hs + cur * 2048 + (bg * 4 + 1) * 256);
            const float4* h2 = (const float4*)(hs + cur * 2048 + (bg * 4 + 2) * 256);
            const float4* h3 = (const float4*)(hs + cur * 2048 + (bg * 4 + 3) * 256);
#pragma unroll 4
            for (int k4 = 0; k4 < 64; ++k4) {
                float4 wv = sW4[k4 * 128 + rr];
                float4 ha = h0[k4], hb = h1[k4], hc = h2[k4], hd = h3[k4];
                acc0 = fmaf(wv.x, ha.x, acc0); acc0 = fmaf(wv.y, ha.y, acc0);
                acc0 = fmaf(wv.z, ha.z, acc0); acc0 = fmaf(wv.w, ha.w, acc0);
                acc1 = fmaf(wv.x, hb.x, acc1); acc1 = fmaf(wv.y, hb.y, acc1);
                acc1 = fmaf(wv.z, hb.z, acc1); acc1 = fmaf(wv.w, hb.w, acc1);
                acc2v = fmaf(wv.x, hc.x, acc2v); acc2v = fmaf(wv.y, hc.y, acc2v);
                acc2v = fmaf(wv.z, hc.z, acc2v); acc2v = fmaf(wv.w, hc.w, acc2v);
                acc3 = fmaf(wv.x, hd.x, acc3); acc3 = fmaf(wv.y, hd.y, acc3);
                acc3 = fmaf(wv.z, hd.z, acc3); acc3 = fmaf(wv.w, hd.w, acc3);
            }
        }
        gs[(bg * 4 + 0) * 128 + rr] = acc0 + gi0;
        gs[(bg * 4 + 1) * 128 + rr] = acc1 + gi1;
        gs[(bg * 4 + 2) * 128 + rr] = acc2v + gi2;
        gs[(bg * 4 + 3) * 128 + rr] = acc3 + gi3;
        __syncthreads();

        // activation for (batch ab, col j = 32*rank + aj)
        {
            float iv = sigf(gs[ab * 128 + aj]);
            float fv = sigf(gs[ab * 128 + 32 + aj]);
            float gv = tanhf(gs[ab * 128 + 64 + aj]);
            float ov = sigf(gs[ab * 128 + 96 + aj]);
            c_reg = fv * c_reg + iv * gv;
            float h = ov * tanhf(c_reg);
            ghout[(size_t)t * NH] = h;
            // broadcast h chunk into every CTA's hs[nxt]
            uint32_t off = (uint32_t)(nxt * 2048 + ab * 256 + 32 * (int)rank + aj) * 4u;
#pragma unroll
            for (int r = 0; r < 8; ++r)
                asm volatile("st.shared::cluster.f32 [%0], %1;"
                             :: "r"(rdst[r] + off), "f"(h) : "memory");
        }
        asm volatile("barrier.cluster.arrive.aligned;" ::: "memory");
        asm volatile("barrier.cluster.wait.aligned;" ::: "memory");
    }
}

// ---------------------------------------------------------------------------
// Kernel 3: emissions. One warp per (b,t); lane = tag.
// ---------------------------------------------------------------------------
__global__ void __launch_bounds__(256) emissions_kernel(
    const int* __restrict__ lens, const float* __restrict__ b_out)
{
    const int item = blockIdx.x * 8 + (threadIdx.x >> 5);
    const int lane = threadIdx.x & 31;
    const int b = item >> 8, t = item & 255;
    const int len = lens[b];
    const int tb = (t < len) ? (len - 1 - t) : t;

    const float* hf = g_h + ((size_t)0 * NB + b) * NT * NH + (size_t)t * NH;
    const float* hb = g_h + ((size_t)1 * NB + b) * NT * NH + (size_t)tb * NH;
    const float* __restrict__ wT = g_wOutT;

    float acc = b_out[lane];
#pragma unroll 4
    for (int k4 = 0; k4 < 64; ++k4) {
        float4 h = *(const float4*)(hf + k4 * 4);
        acc = fmaf(h.x, wT[(k4 * 4 + 0) * NC + lane], acc);
        acc = fmaf(h.y, wT[(k4 * 4 + 1) * NC + lane], acc);
        acc = fmaf(h.z, wT[(k4 * 4 + 2) * NC + lane], acc);
        acc = fmaf(h.w, wT[(k4 * 4 + 3) * NC + lane], acc);
    }
#pragma unroll 4
    for (int k4 = 0; k4 < 64; ++k4) {
        float4 h = *(const float4*)(hb + k4 * 4);
        acc = fmaf(h.x, wT[(NH + k4 * 4 + 0) * NC + lane], acc);
        acc = fmaf(h.y, wT[(NH + k4 * 4 + 1) * NC + lane], acc);
        acc = fmaf(h.z, wT[(NH + k4 * 4 + 2) * NC + lane], acc);
        acc = fmaf(h.w, wT[(NH + k4 * 4 + 3) * NC + lane], acc);
    }
    g_em[(size_t)item * NC + lane] = acc;
}

// ---------------------------------------------------------------------------
// Kernel 4: Viterbi decode. One warp per batch element; lane = tag.
// ---------------------------------------------------------------------------
__global__ void __launch_bounds__(32) viterbi_kernel(
    const int* __restrict__ lens,
    const float* __restrict__ start_trans, const float* __restrict__ end_trans,
    const float* __restrict__ trans, float* __restrict__ out)
{
    const int b = blockIdx.x;
    const int lane = threadIdx.x;

    __shared__ int hist[NT - 1][NC];

    float tr[NC];  // tr[cp] = trans[cp][lane]
#pragma unroll
    for (int cp = 0; cp < NC; ++cp) tr[cp] = trans[cp * NC + lane];

    const int len = lens[b];
    const float* emp = g_em + (size_t)b * NT * NC;
    float score = start_trans[lane] + emp[lane];
    float em_next = emp[NC + lane];

    for (int t = 1; t < NT; ++t) {
        float best = -1e30f;
        int bp = 0;
#pragma unroll
        for (int cp = 0; cp < NC; ++cp) {
            float sc = __shfl_sync(0xffffffffu, score, cp) + tr[cp];
            if (sc > best) { best = sc; bp = cp; }
        }
        hist[t - 1][lane] = bp;
        float em_cur = em_next;
        if (t + 1 < NT) em_next = emp[(t + 1) * NC + lane];
        if (t < len) score = best + em_cur;
    }
    score += end_trans[lane];

    float v = score;
    int idx = lane;
#pragma unroll
    for (int off = 16; off; off >>= 1) {
        float v2 = __shfl_xor_sync(0xffffffffu, v, off);
        int i2 = __shfl_xor_sync(0xffffffffu, idx, off);
        if (v2 > v || (v2 == v && i2 < idx)) { v = v2; idx = i2; }
    }

    if (lane == 0) {
        out[NB * NT + b] = v;
        int tag = idx;
        out[(size_t)b * NT + (NT - 1)] = (float)tag;
        for (int t = NT - 2; t >= 0; --t) {
            if (t < len - 1) tag = hist[t][tag];
            out[(size_t)b * NT + t] = (float)tag;
        }
    }
}

// ---------------------------------------------------------------------------
extern "C" void kernel_launch(void* const* d_in, const int* in_sizes, int n_in,
                              void* d_out, int out_size)
{
    const int*   sent   = (const int*)d_in[0];
    const int*   lens   = (const int*)d_in[1];
    const float* emb    = (const float*)d_in[2];
    const float* w_ih_f = (const float*)d_in[3];
    const float* w_hh_f = (const float*)d_in[4];
    const float* b_ih_f = (const float*)d_in[5];
    const float* b_hh_f = (const float*)d_in[6];
    const float* w_ih_b = (const float*)d_in[7];
    const float* w_hh_b = (const float*)d_in[8];
    const float* b_ih_b = (const float*)d_in[9];
    const float* b_hh_b = (const float*)d_in[10];
    const float* w_out  = (const float*)d_in[11];
    const float* b_out  = (const float*)d_in[12];
    const float* start_trans = (const float*)d_in[13];
    const float* end_trans   = (const float*)d_in[14];
    const float* trans       = (const float*)d_in[15];
    float* out = (float*)d_out;

    cudaFuncSetAttribute(lstm_cluster_kernel,
                         cudaFuncAttributeMaxDynamicSharedMemorySize, LSMEM_BYTES);

    dim3 tb(32, 8);
    transpose_wout_kernel<<<dim3((2 * NH) / 32, 1, 1), tb>>>(w_out);

    dim3 g1(128, 16);  // M tiles x (2 dirs * 8 N tiles)
    input_proj_kernel<<<g1, 256>>>(sent, lens, emb,
                                   w_ih_f, b_ih_f, b_hh_f,
                                   w_ih_b, b_ih_b, b_hh_b);
    lstm_cluster_kernel<<<128, 256, LSMEM_BYTES>>>(w_hh_f, w_hh_b);
    emissions_kernel<<<NB * NT / 8, 256>>>(lens, b_out);
    viterbi_kernel<<<NB, 32>>>(lens, start_trans, end_trans, trans, out);
}

// round 7
// speedup vs baseline: 1.0053x; 1.0053x over previous
#include <cuda_runtime.h>
#include <stdint.h>
#include <math.h>

// Problem constants
constexpr int NB = 64;    // batch
constexpr int NT = 256;   // time
constexpr int ND = 256;   // embed dim
constexpr int NH = 256;   // hidden per direction
constexpr int NC = 32;    // tags
constexpr int NG = 1024;  // 4*NH gate rows

// Scratch (static device allocations; no cudaMalloc allowed)
__device__ __align__(16) float g_gates[(size_t)2 * NB * NT * NG]; // input-projected gate preacts per dir
__device__ __align__(16) float g_h[(size_t)2 * NB * NT * NH];     // LSTM outputs per dir (bwd in reversed time)
__device__ __align__(16) float g_em[(size_t)NB * NT * NC];        // emissions
__device__ __align__(16) float g_wOutT[(size_t)2 * NH * NC];      // w_out transposed: [k][c]

__device__ __forceinline__ float sigf(float x) { return 1.0f / (1.0f + __expf(-x)); }

// ---------------------------------------------------------------------------
// Kernel 0: transpose w_out [32][512] -> g_wOutT[512][32]
// ---------------------------------------------------------------------------
__global__ void transpose_wout_kernel(const float* __restrict__ w)
{
    __shared__ float tile[32][33];
    const int k0 = blockIdx.x * 32;
    const int tx = threadIdx.x, ty = threadIdx.y;
#pragma unroll
    for (int i = 0; i < 32; i += 8)
        tile[ty + i][tx] = w[(size_t)(ty + i) * (2 * NH) + k0 + tx];
    __syncthreads();
#pragma unroll
    for (int i = 0; i < 32; i += 8)
        g_wOutT[(size_t)(k0 + ty + i) * NC + tx] = tile[tx][ty + i];
}

// ---------------------------------------------------------------------------
// Kernel 1: embedding gather + input projection for both directions.
// SGEMM: BM=128, BN=128, BK=16, 256 threads, 8x8 per-thread microtile (plain FFMA).
// ---------------------------------------------------------------------------
__global__ void __launch_bounds__(256) input_proj_kernel(
    const int* __restrict__ sent, const int* __restrict__ lens,
    const float* __restrict__ emb,
    const float* __restrict__ w_f, const float* __restrict__ bi_f, const float* __restrict__ bh_f,
    const float* __restrict__ w_b, const float* __restrict__ bi_b, const float* __restrict__ bh_b)
{
    const int dir = blockIdx.y >> 3;
    const int n0  = (blockIdx.y & 7) * 128;
    const int m0  = blockIdx.x * 128;

    const float* __restrict__ W  = dir ? w_b  : w_f;
    const float* __restrict__ BI = dir ? bi_b : bi_f;
    const float* __restrict__ BH = dir ? bh_b : bh_f;

    __shared__ __align__(16) float As[16][128];
    __shared__ __align__(16) float Bs[16][128];
    __shared__ int toks[128];

    const int tid = threadIdx.x;
    if (tid < 128) {
        int m = m0 + tid;
        int b = m >> 8, t = m & 255;
        int ts = t;
        if (dir) { int len = lens[b]; if (t < len) ts = len - 1 - t; }
        toks[tid] = sent[b * NT + ts];
    }
    __syncthreads();

    const int lrow2 = tid >> 2;   // 0..63
    const int lane4 = tid & 3;    // 0..3
    const int row0 = lrow2, row1 = lrow2 + 64;
    const float* arow0 = emb + (size_t)toks[row0] * ND + lane4 * 4;
    const float* arow1 = emb + (size_t)toks[row1] * ND + lane4 * 4;
    const float* brow0 = W + (size_t)(n0 + row0) * ND + lane4 * 4;
    const float* brow1 = W + (size_t)(n0 + row1) * ND + lane4 * 4;

    const int tx = tid & 15, ty = tid >> 4;

    float acc[8][8];
#pragma unroll
    for (int i = 0; i < 8; i++)
#pragma unroll
        for (int j = 0; j < 8; j++) acc[i][j] = 0.0f;

    for (int kk = 0; kk < ND; kk += 16) {
        float4 a0 = *(const float4*)(arow0 + kk);
        float4 a1 = *(const float4*)(arow1 + kk);
        float4 b0 = *(const float4*)(brow0 + kk);
        float4 b1 = *(const float4*)(brow1 + kk);
        As[lane4 * 4 + 0][row0] = a0.x; As[lane4 * 4 + 1][row0] = a0.y;
        As[lane4 * 4 + 2][row0] = a0.z; As[lane4 * 4 + 3][row0] = a0.w;
        As[lane4 * 4 + 0][row1] = a1.x; As[lane4 * 4 + 1][row1] = a1.y;
        As[lane4 * 4 + 2][row1] = a1.z; As[lane4 * 4 + 3][row1] = a1.w;
        Bs[lane4 * 4 + 0][row0] = b0.x; Bs[lane4 * 4 + 1][row0] = b0.y;
        Bs[lane4 * 4 + 2][row0] = b0.z; Bs[lane4 * 4 + 3][row0] = b0.w;
        Bs[lane4 * 4 + 0][row1] = b1.x; Bs[lane4 * 4 + 1][row1] = b1.y;
        Bs[lane4 * 4 + 2][row1] = b1.z; Bs[lane4 * 4 + 3][row1] = b1.w;
        __syncthreads();
#pragma unroll
        for (int k = 0; k < 16; ++k) {
            float4 av0 = *(const float4*)&As[k][ty * 8];
            float4 av1 = *(const float4*)&As[k][ty * 8 + 4];
            float4 bv0 = *(const float4*)&Bs[k][tx * 8];
            float4 bv1 = *(const float4*)&Bs[k][tx * 8 + 4];
            float a[8] = {av0.x, av0.y, av0.z, av0.w, av1.x, av1.y, av1.z, av1.w};
            float bb[8] = {bv0.x, bv0.y, bv0.z, bv0.w, bv1.x, bv1.y, bv1.z, bv1.w};
#pragma unroll
            for (int i = 0; i < 8; i++)
#pragma unroll
                for (int j = 0; j < 8; j++) acc[i][j] = fmaf(a[i], bb[j], acc[i][j]);
        }
        __syncthreads();
    }

    float bias[8];
#pragma unroll
    for (int j = 0; j < 8; j++) {
        int n = n0 + tx * 8 + j;
        bias[j] = BI[n] + BH[n];
    }
#pragma unroll
    for (int i = 0; i < 8; i++) {
        int m = m0 + ty * 8 + i;
        float* o = g_gates + ((size_t)dir * (NB * NT) + m) * NG + n0 + tx * 8;
        float4 s0, s1;
        s0.x = acc[i][0] + bias[0]; s0.y = acc[i][1] + bias[1];
        s0.z = acc[i][2] + bias[2]; s0.w = acc[i][3] + bias[3];
        s1.x = acc[i][4] + bias[4]; s1.y = acc[i][5] + bias[5];
        s1.z = acc[i][6] + bias[6]; s1.w = acc[i][7] + bias[7];
        *(float4*)o = s0;
        *(float4*)(o + 4) = s1;
    }
}

// ---------------------------------------------------------------------------
// Kernel 2: weight-stationary cluster LSTM.
// 128 CTAs = 16 clusters x 8. Cluster = (dir, batch-group of 8).
// CTA rank r owns h-cols [32r, 32r+32): 128 gate rows x 256 k = 128KB in SMEM.
// Per step: compute own gate slice for 8 batches, activate, exchange h chunks
// via DSMEM writes, barrier.cluster.
// ---------------------------------------------------------------------------
constexpr int LSMEM_FLOATS = 32768 /*weights*/ + 4096 /*hs dbl buf*/ + 1024 /*gs*/;
constexpr int LSMEM_BYTES = LSMEM_FLOATS * 4;

__global__ void __launch_bounds__(256, 1) __cluster_dims__(8, 1, 1)
lstm_cluster_kernel(const float* __restrict__ w_hh_f, const float* __restrict__ w_hh_b)
{
    extern __shared__ __align__(16) float smem[];
    float* sW = smem;                  // [k4][128 rows][4 k]  (32768 floats)
    float* hs = smem + 32768;          // [2][8 batches][256]  (4096 floats)
    float* gs = smem + 32768 + 4096;   // [8 batches][128 rows] (1024 floats)

    const int tid = threadIdx.x;
    uint32_t rank;
    asm("mov.u32 %0, %%cluster_ctarank;" : "=r"(rank));
    const int cl = blockIdx.x >> 3;
    const int dir = cl & 1;
    const int bgrp = cl >> 1;          // 0..7 -> batches bgrp*8 .. +8

    const float* __restrict__ whh = dir ? w_hh_b : w_hh_f;

    // ---- Preload weight slice into SMEM: row rr -> gate=rr>>5, j=32*rank+(rr&31)
    for (int idx = tid; idx < 128 * 256; idx += 256) {
        int rr = idx >> 8, k = idx & 255;
        int gate = rr >> 5;
        int g = gate * 256 + 32 * (int)rank + (rr & 31);
        sW[(k >> 2) * 512 + rr * 4 + (k & 3)] = whh[(size_t)g * NH + k];
    }
    // init h buffers (both phases)
    for (int idx = tid; idx < 4096; idx += 256) hs[idx] = 0.0f;

    // shared-address bases for DSMEM exchange
    uint32_t hs_sh;
    {
        asm("{ .reg .u64 t; cvta.to.shared.u64 t, %1; cvt.u32.u64 %0, t; }"
            : "=r"(hs_sh) : "l"(hs));
    }
    uint32_t rdst[8];
#pragma unroll
    for (int r = 0; r < 8; ++r)
        asm("mapa.shared::cluster.u32 %0, %1, %2;" : "=r"(rdst[r]) : "r"(hs_sh), "r"(r));

    // gate-compute mapping: warp w: row-group rg=w&3, batch-group bg=w>>2
    const int w = tid >> 5, l = tid & 31;
    const int rg = w & 3, bg = w >> 2;
    const int rr = rg * 32 + l;               // 0..127 ; gate = rg
    const int grow = rg * 256 + 32 * (int)rank + l;
    const float4* sW4 = (const float4*)sW;    // sW4[k4*128 + rr]

    const float* gin[4];
#pragma unroll
    for (int i = 0; i < 4; ++i)
        gin[i] = g_gates + ((size_t)(dir * NB + bgrp * 8 + bg * 4 + i)) * NT * NG + grow;

    // activation mapping: b = tid>>5, j = tid&31 ; cell state in register
    const int ab = tid >> 5, aj = tid & 31;
    float c_reg = 0.0f;
    float* ghout = g_h + ((size_t)(dir * NB + bgrp * 8 + ab)) * (NT * NH) + 32 * (int)rank + aj;

    // all CTAs: weights + h init visible cluster-wide before first exchange
    asm volatile("barrier.cluster.arrive.aligned;" ::: "memory");
    asm volatile("barrier.cluster.wait.aligned;" ::: "memory");

    for (int t = 0; t < NT; ++t) {
        const int cur = t & 1, nxt = cur ^ 1;
        // issue gin loads early (consumed after k-loop)
        float gi0 = gin[0][(size_t)t * NG];
        float gi1 = gin[1][(size_t)t * NG];
        float gi2 = gin[2][(size_t)t * NG];
        float gi3 = gin[3][(size_t)t * NG];

        float acc0 = 0.f, acc1 = 0.f, acc2v = 0.f, acc3 = 0.f;
        if (t > 0) {
            const float4* h0 = (const float4*)(hs + cur * 2048 + (bg * 4 + 0) * 256);
            const float4* h1 = (const float4*)(hs + cur * 2048 + (bg * 4 + 1) * 256);
            const float4* h2 = (const float4*)(hs + cur * 2048 + (bg * 4 + 2) * 256);
            const float4* h3 = (const float4*)(hs + cur * 2048 + (bg * 4 + 3) * 256);
#pragma unroll 4
            for (int k4 = 0; k4 < 64; ++k4) {
                float4 wv = sW4[k4 * 128 + rr];
                float4 ha = h0[k4], hb = h1[k4], hc = h2[k4], hd = h3[k4];
                acc0 = fmaf(wv.x, ha.x, acc0); acc0 = fmaf(wv.y, ha.y, acc0);
                acc0 = fmaf(wv.z, ha.z, acc0); acc0 = fmaf(wv.w, ha.w, acc0);
                acc1 = fmaf(wv.x, hb.x, acc1); acc1 = fmaf(wv.y, hb.y, acc1);
                acc1 = fmaf(wv.z, hb.z, acc1); acc1 = fmaf(wv.w, hb.w, acc1);
                acc2v = fmaf(wv.x, hc.x, acc2v); acc2v = fmaf(wv.y, hc.y, acc2v);
                acc2v = fmaf(wv.z, hc.z, acc2v); acc2v = fmaf(wv.w, hc.w, acc2v);
                acc3 = fmaf(wv.x, hd.x, acc3); acc3 = fmaf(wv.y, hd.y, acc3);
                acc3 = fmaf(wv.z, hd.z, acc3); acc3 = fmaf(wv.w, hd.w, acc3);
            }
        }
        gs[(bg * 4 + 0) * 128 + rr] = acc0 + gi0;
        gs[(bg * 4 + 1) * 128 + rr] = acc1 + gi1;
        gs[(bg * 4 + 2) * 128 + rr] = acc2v + gi2;
        gs[(bg * 4 + 3) * 128 + rr] = acc3 + gi3;
        __syncthreads();

        // activation for (batch ab, col j = 32*rank + aj)
        {
            float iv = sigf(gs[ab * 128 + aj]);
            float fv = sigf(gs[ab * 128 + 32 + aj]);
            float gv = tanhf(gs[ab * 128 + 64 + aj]);
            float ov = sigf(gs[ab * 128 + 96 + aj]);
            c_reg = fv * c_reg + iv * gv;
            float h = ov * tanhf(c_reg);
            ghout[(size_t)t * NH] = h;
            // broadcast h chunk into every CTA's hs[nxt]
            uint32_t off = (uint32_t)(nxt * 2048 + ab * 256 + 32 * (int)rank + aj) * 4u;
#pragma unroll
            for (int r = 0; r < 8; ++r)
                asm volatile("st.shared::cluster.f32 [%0], %1;"
                             :: "r"(rdst[r] + off), "f"(h) : "memory");
        }
        asm volatile("barrier.cluster.arrive.aligned;" ::: "memory");
        asm volatile("barrier.cluster.wait.aligned;" ::: "memory");
    }
}

// ---------------------------------------------------------------------------
// Kernel 3: emissions. One warp per (b,t); lane = tag.
// 4 independent accumulator chains (breaks serial FMA latency chain).
// ---------------------------------------------------------------------------
__global__ void __launch_bounds__(256) emissions_kernel(
    const int* __restrict__ lens, const float* __restrict__ b_out)
{
    const int item = blockIdx.x * 8 + (threadIdx.x >> 5);
    const int lane = threadIdx.x & 31;
    const int b = item >> 8, t = item & 255;
    const int len = lens[b];
    const int tb = (t < len) ? (len - 1 - t) : t;

    const float* hf = g_h + ((size_t)0 * NB + b) * NT * NH + (size_t)t * NH;
    const float* hb = g_h + ((size_t)1 * NB + b) * NT * NH + (size_t)tb * NH;
    const float* __restrict__ wT = g_wOutT;

    float acc0 = b_out[lane], acc1 = 0.f, acc2 = 0.f, acc3 = 0.f;
#pragma unroll 4
    for (int k16 = 0; k16 < 16; ++k16) {
        float4 ha = *(const float4*)(hf + k16 * 16);
        float4 hbv = *(const float4*)(hf + k16 * 16 + 4);
        float4 hc = *(const float4*)(hf + k16 * 16 + 8);
        float4 hd = *(const float4*)(hf + k16 * 16 + 12);
        const float* w0 = wT + (k16 * 16) * NC + lane;
        acc0 = fmaf(ha.x, w0[0 * NC], acc0);  acc1 = fmaf(ha.y, w0[1 * NC], acc1);
        acc2 = fmaf(ha.z, w0[2 * NC], acc2);  acc3 = fmaf(ha.w, w0[3 * NC], acc3);
        acc0 = fmaf(hbv.x, w0[4 * NC], acc0); acc1 = fmaf(hbv.y, w0[5 * NC], acc1);
        acc2 = fmaf(hbv.z, w0[6 * NC], acc2); acc3 = fmaf(hbv.w, w0[7 * NC], acc3);
        acc0 = fmaf(hc.x, w0[8 * NC], acc0);  acc1 = fmaf(hc.y, w0[9 * NC], acc1);
        acc2 = fmaf(hc.z, w0[10 * NC], acc2); acc3 = fmaf(hc.w, w0[11 * NC], acc3);
        acc0 = fmaf(hd.x, w0[12 * NC], acc0); acc1 = fmaf(hd.y, w0[13 * NC], acc1);
        acc2 = fmaf(hd.z, w0[14 * NC], acc2); acc3 = fmaf(hd.w, w0[15 * NC], acc3);
    }
#pragma unroll 4
    for (int k16 = 0; k16 < 16; ++k16) {
        float4 ha = *(const float4*)(hb + k16 * 16);
        float4 hbv = *(const float4*)(hb + k16 * 16 + 4);
        float4 hc = *(const float4*)(hb + k16 * 16 + 8);
        float4 hd = *(const float4*)(hb + k16 * 16 + 12);
        const float* w0 = wT + (NH + k16 * 16) * NC + lane;
        acc0 = fmaf(ha.x, w0[0 * NC], acc0);  acc1 = fmaf(ha.y, w0[1 * NC], acc1);
        acc2 = fmaf(ha.z, w0[2 * NC], acc2);  acc3 = fmaf(ha.w, w0[3 * NC], acc3);
        acc0 = fmaf(hbv.x, w0[4 * NC], acc0); acc1 = fmaf(hbv.y, w0[5 * NC], acc1);
        acc2 = fmaf(hbv.z, w0[6 * NC], acc2); acc3 = fmaf(hbv.w, w0[7 * NC], acc3);
        acc0 = fmaf(hc.x, w0[8 * NC], acc0);  acc1 = fmaf(hc.y, w0[9 * NC], acc1);
        acc2 = fmaf(hc.z, w0[10 * NC], acc2); acc3 = fmaf(hc.w, w0[11 * NC], acc3);
        acc0 = fmaf(hd.x, w0[12 * NC], acc0); acc1 = fmaf(hd.y, w0[13 * NC], acc1);
        acc2 = fmaf(hd.z, w0[14 * NC], acc2); acc3 = fmaf(hd.w, w0[15 * NC], acc3);
    }
    g_em[(size_t)item * NC + lane] = (acc0 + acc1) + (acc2 + acc3);
}

// ---------------------------------------------------------------------------
// Kernel 4: Viterbi decode. One warp per batch element; lane = tag.
// ---------------------------------------------------------------------------
__global__ void __launch_bounds__(32) viterbi_kernel(
    const int* __restrict__ lens,
    const float* __restrict__ start_trans, const float* __restrict__ end_trans,
    const float* __restrict__ trans, float* __restrict__ out)
{
    const int b = blockIdx.x;
    const int lane = threadIdx.x;

    __shared__ int hist[NT - 1][NC];

    float tr[NC];  // tr[cp] = trans[cp][lane]
#pragma unroll
    for (int cp = 0; cp < NC; ++cp) tr[cp] = trans[cp * NC + lane];

    const int len = lens[b];
    const float* emp = g_em + (size_t)b * NT * NC;
    float score = start_trans[lane] + emp[lane];
    float em_next = emp[NC + lane];

    for (int t = 1; t < NT; ++t) {
        float best = -1e30f;
        int bp = 0;
#pragma unroll
        for (int cp = 0; cp < NC; ++cp) {
            float sc = __shfl_sync(0xffffffffu, score, cp) + tr[cp];
            if (sc > best) { best = sc; bp = cp; }
        }
        hist[t - 1][lane] = bp;
        float em_cur = em_next;
        if (t + 1 < NT) em_next = emp[(t + 1) * NC + lane];
        if (t < len) score = best + em_cur;
    }
    score += end_trans[lane];

    float v = score;
    int idx = lane;
#pragma unroll
    for (int off = 16; off; off >>= 1) {
        float v2 = __shfl_xor_sync(0xffffffffu, v, off);
        int i2 = __shfl_xor_sync(0xffffffffu, idx, off);
        if (v2 > v || (v2 == v && i2 < idx)) { v = v2; idx = i2; }
    }

    if (lane == 0) {
        out[NB * NT + b] = v;
        int tag = idx;
        out[(size_t)b * NT + (NT - 1)] = (float)tag;
        for (int t = NT - 2; t >= 0; --t) {
            if (t < len - 1) tag = hist[t][tag];
            out[(size_t)b * NT + t] = (float)tag;
        }
    }
}

// ---------------------------------------------------------------------------
extern "C" void kernel_launch(void* const* d_in, const int* in_sizes, int n_in,
                              void* d_out, int out_size)
{
    const int*   sent   = (const int*)d_in[0];
    const int*   lens   = (const int*)d_in[1];
    const float* emb    = (const float*)d_in[2];
    const float* w_ih_f = (const float*)d_in[3];
    const float* w_hh_f = (const float*)d_in[4];
    const float* b_ih_f = (const float*)d_in[5];
    const float* b_hh_f = (const float*)d_in[6];
    const float* w_ih_b = (const float*)d_in[7];
    const float* w_hh_b = (const float*)d_in[8];
    const float* b_ih_b = (const float*)d_in[9];
    const float* b_hh_b = (const float*)d_in[10];
    const float* w_out  = (const float*)d_in[11];
    const float* b_out  = (const float*)d_in[12];
    const float* start_trans = (const float*)d_in[13];
    const float* end_trans   = (const float*)d_in[14];
    const float* trans       = (const float*)d_in[15];
    float* out = (float*)d_out;

    cudaFuncSetAttribute(lstm_cluster_kernel,
                         cudaFuncAttributeMaxDynamicSharedMemorySize, LSMEM_BYTES);

    dim3 tb(32, 8);
    transpose_wout_kernel<<<dim3((2 * NH) / 32, 1, 1), tb>>>(w_out);

    dim3 g1(128, 16);  // M tiles x (2 dirs * 8 N tiles)
    input_proj_kernel<<<g1, 256>>>(sent, lens, emb,
                                   w_ih_f, b_ih_f, b_hh_f,
                                   w_ih_b, b_ih_b, b_hh_b);
    lstm_cluster_kernel<<<128, 256, LSMEM_BYTES>>>(w_hh_f, w_hh_b);
    emissions_kernel<<<NB * NT / 8, 256>>>(lens, b_out);
    viterbi_kernel<<<NB, 32>>>(lens, start_trans, end_trans, trans, out);
}

// round 8
// speedup vs baseline: 1.0732x; 1.0676x over previous
#include <cuda_runtime.h>
#include <stdint.h>
#include <math.h>

// Problem constants
constexpr int NB = 64;    // batch
constexpr int NT = 256;   // time
constexpr int ND = 256;   // embed dim
constexpr int NH = 256;   // hidden per direction
constexpr int NC = 32;    // tags
constexpr int NG = 1024;  // 4*NH gate rows

// Scratch (static device allocations; no cudaMalloc allowed)
__device__ __align__(16) float g_gates[(size_t)2 * NB * NT * NG];
__device__ __align__(16) float g_h[(size_t)2 * NB * NT * NH];
__device__ __align__(16) float g_em[(size_t)NB * NT * NC];
__device__ __align__(16) float g_wOutT[(size_t)2 * NH * NC];

__device__ __forceinline__ float sigf(float x) { return 1.0f / (1.0f + __expf(-x)); }

// ---------------------------------------------------------------------------
// Kernel 0: transpose w_out [32][512] -> g_wOutT[512][32]
// ---------------------------------------------------------------------------
__global__ void transpose_wout_kernel(const float* __restrict__ w)
{
    __shared__ float tile[32][33];
    const int k0 = blockIdx.x * 32;
    const int tx = threadIdx.x, ty = threadIdx.y;
#pragma unroll
    for (int i = 0; i < 32; i += 8)
        tile[ty + i][tx] = w[(size_t)(ty + i) * (2 * NH) + k0 + tx];
    __syncthreads();
#pragma unroll
    for (int i = 0; i < 32; i += 8)
        g_wOutT[(size_t)(k0 + ty + i) * NC + tx] = tile[tx][ty + i];
}

// ---------------------------------------------------------------------------
// Kernel 1: embedding gather + input projection (both directions).
// SGEMM: BM=128, BN=128, BK=16, 256 threads, 8x8 microtile (plain FFMA).
// ---------------------------------------------------------------------------
__global__ void __launch_bounds__(256) input_proj_kernel(
    const int* __restrict__ sent, const int* __restrict__ lens,
    const float* __restrict__ emb,
    const float* __restrict__ w_f, const float* __restrict__ bi_f, const float* __restrict__ bh_f,
    const float* __restrict__ w_b, const float* __restrict__ bi_b, const float* __restrict__ bh_b)
{
    const int dir = blockIdx.y >> 3;
    const int n0  = (blockIdx.y & 7) * 128;
    const int m0  = blockIdx.x * 128;

    const float* __restrict__ W  = dir ? w_b  : w_f;
    const float* __restrict__ BI = dir ? bi_b : bi_f;
    const float* __restrict__ BH = dir ? bh_b : bh_f;

    __shared__ __align__(16) float As[16][128];
    __shared__ __align__(16) float Bs[16][128];
    __shared__ int toks[128];

    const int tid = threadIdx.x;
    if (tid < 128) {
        int m = m0 + tid;
        int b = m >> 8, t = m & 255;
        int ts = t;
        if (dir) { int len = lens[b]; if (t < len) ts = len - 1 - t; }
        toks[tid] = sent[b * NT + ts];
    }
    __syncthreads();

    const int lrow2 = tid >> 2;
    const int lane4 = tid & 3;
    const int row0 = lrow2, row1 = lrow2 + 64;
    const float* arow0 = emb + (size_t)toks[row0] * ND + lane4 * 4;
    const float* arow1 = emb + (size_t)toks[row1] * ND + lane4 * 4;
    const float* brow0 = W + (size_t)(n0 + row0) * ND + lane4 * 4;
    const float* brow1 = W + (size_t)(n0 + row1) * ND + lane4 * 4;

    const int tx = tid & 15, ty = tid >> 4;

    float acc[8][8];
#pragma unroll
    for (int i = 0; i < 8; i++)
#pragma unroll
        for (int j = 0; j < 8; j++) acc[i][j] = 0.0f;

    for (int kk = 0; kk < ND; kk += 16) {
        float4 a0 = *(const float4*)(arow0 + kk);
        float4 a1 = *(const float4*)(arow1 + kk);
        float4 b0 = *(const float4*)(brow0 + kk);
        float4 b1 = *(const float4*)(brow1 + kk);
        As[lane4 * 4 + 0][row0] = a0.x; As[lane4 * 4 + 1][row0] = a0.y;
        As[lane4 * 4 + 2][row0] = a0.z; As[lane4 * 4 + 3][row0] = a0.w;
        As[lane4 * 4 + 0][row1] = a1.x; As[lane4 * 4 + 1][row1] = a1.y;
        As[lane4 * 4 + 2][row1] = a1.z; As[lane4 * 4 + 3][row1] = a1.w;
        Bs[lane4 * 4 + 0][row0] = b0.x; Bs[lane4 * 4 + 1][row0] = b0.y;
        Bs[lane4 * 4 + 2][row0] = b0.z; Bs[lane4 * 4 + 3][row0] = b0.w;
        Bs[lane4 * 4 + 0][row1] = b1.x; Bs[lane4 * 4 + 1][row1] = b1.y;
        Bs[lane4 * 4 + 2][row1] = b1.z; Bs[lane4 * 4 + 3][row1] = b1.w;
        __syncthreads();
#pragma unroll
        for (int k = 0; k < 16; ++k) {
            float4 av0 = *(const float4*)&As[k][ty * 8];
            float4 av1 = *(const float4*)&As[k][ty * 8 + 4];
            float4 bv0 = *(const float4*)&Bs[k][tx * 8];
            float4 bv1 = *(const float4*)&Bs[k][tx * 8 + 4];
            float a[8] = {av0.x, av0.y, av0.z, av0.w, av1.x, av1.y, av1.z, av1.w};
            float bb[8] = {bv0.x, bv0.y, bv0.z, bv0.w, bv1.x, bv1.y, bv1.z, bv1.w};
#pragma unroll
            for (int i = 0; i < 8; i++)
#pragma unroll
                for (int j = 0; j < 8; j++) acc[i][j] = fmaf(a[i], bb[j], acc[i][j]);
        }
        __syncthreads();
    }

    float bias[8];
#pragma unroll
    for (int j = 0; j < 8; j++) {
        int n = n0 + tx * 8 + j;
        bias[j] = BI[n] + BH[n];
    }
#pragma unroll
    for (int i = 0; i < 8; i++) {
        int m = m0 + ty * 8 + i;
        float* o = g_gates + ((size_t)dir * (NB * NT) + m) * NG + n0 + tx * 8;
        float4 s0, s1;
        s0.x = acc[i][0] + bias[0]; s0.y = acc[i][1] + bias[1];
        s0.z = acc[i][2] + bias[2]; s0.w = acc[i][3] + bias[3];
        s1.x = acc[i][4] + bias[4]; s1.y = acc[i][5] + bias[5];
        s1.z = acc[i][6] + bias[6]; s1.w = acc[i][7] + bias[7];
        *(float4*)o = s0;
        *(float4*)(o + 4) = s1;
    }
}

// ---------------------------------------------------------------------------
// Kernel 2: weight-stationary cluster LSTM with TX-MBARRIER sync (no
// barrier.cluster in the loop, no per-step L1 flush).
// 128 CTAs = 16 clusters x 8. Cluster = (dir, batch-group of 8).
// CTA rank r owns h-cols [32r,32r+32): 128 gate rows x 256 k in SMEM (128KB).
// Per step: gate slice for 8 batches -> activation -> h broadcast via
// st.async.shared::cluster with mbarrier complete_tx (8192 B expected/phase).
// ---------------------------------------------------------------------------
constexpr int LS_W  = 32768;                 // weight floats
constexpr int LS_H  = 4096;                  // hs double buffer floats
constexpr int LS_G  = 1024;                  // gs floats
constexpr int LS_MBAR_OFF = (LS_W + LS_H + LS_G) * 4;   // byte offset of mb[2]
constexpr int LSMEM_BYTES = LS_MBAR_OFF + 16;
constexpr unsigned TXBYTES = 2048u * 4u;     // per-phase expected bytes

#define MBWAIT_CL(mbar, par) do {                                              \
    asm volatile(                                                              \
        "{\n\t.reg .pred P1;\n\t"                                              \
        "WL%=:\n\t"                                                            \
        "mbarrier.try_wait.parity.acquire.cluster.shared::cta.b64 P1, [%0], %1, 0x989680;\n\t" \
        "@P1 bra WD%=;\n\t"                                                    \
        "bra WL%=;\n\t"                                                        \
        "WD%=:\n\t}"                                                           \
        :: "r"(mbar), "r"(par) : "memory");                                    \
} while (0)

__global__ void __launch_bounds__(256, 1) __cluster_dims__(8, 1, 1)
lstm_cluster_kernel(const float* __restrict__ w_hh_f, const float* __restrict__ w_hh_b)
{
    extern __shared__ __align__(16) float smem[];
    float* sW = smem;                  // [k4][128 rows][4 k]
    float* hs = smem + LS_W;           // [2][8 batches][256]
    float* gs = smem + LS_W + LS_H;    // [8 batches][128 rows]

    const int tid = threadIdx.x;
    uint32_t rank;
    asm("mov.u32 %0, %%cluster_ctarank;" : "=r"(rank));
    const int cl = blockIdx.x >> 3;
    const int dir = cl & 1;
    const int bgrp = cl >> 1;

    const float* __restrict__ whh = dir ? w_hh_b : w_hh_f;

    // Preload weight slice: row rr -> gate=rr>>5, col j=32*rank+(rr&31)
    for (int idx = tid; idx < 128 * 256; idx += 256) {
        int rr = idx >> 8, k = idx & 255;
        int gate = rr >> 5;
        int g = gate * 256 + 32 * (int)rank + (rr & 31);
        sW[(k >> 2) * 512 + rr * 4 + (k & 3)] = whh[(size_t)g * NH + k];
    }

    // SMEM u32 addresses
    uint32_t smem_base;
    asm("{ .reg .u64 t; cvta.to.shared.u64 t, %1; cvt.u32.u64 %0, t; }"
        : "=r"(smem_base) : "l"(smem));
    const uint32_t hs_sh = smem_base + (uint32_t)(LS_W * 4);
    const uint32_t mb_sh = smem_base + (uint32_t)LS_MBAR_OFF;

    // Init mbarriers (count=1: the expect_tx arrival) + initial expects
    if (tid == 0) {
        asm volatile("mbarrier.init.shared.b64 [%0], 1;" :: "r"(mb_sh) : "memory");
        asm volatile("mbarrier.init.shared.b64 [%0], 1;" :: "r"(mb_sh + 8) : "memory");
        asm volatile("mbarrier.arrive.expect_tx.shared.b64 _, [%0], %1;"
                     :: "r"(mb_sh), "r"(TXBYTES) : "memory");
        asm volatile("mbarrier.arrive.expect_tx.shared.b64 _, [%0], %1;"
                     :: "r"(mb_sh + 8), "r"(TXBYTES) : "memory");
    }
    __syncthreads();

    // Cluster-wide: inits visible before any st.async arrives
    asm volatile("barrier.cluster.arrive.aligned;" ::: "memory");
    asm volatile("barrier.cluster.wait.aligned;" ::: "memory");

    // mapa'd remote bases (hs and mbar) for all 8 ranks
    uint32_t rhs[8], rmb[8];
#pragma unroll
    for (int r = 0; r < 8; ++r) {
        asm("mapa.shared::cluster.u32 %0, %1, %2;" : "=r"(rhs[r]) : "r"(hs_sh), "r"(r));
        asm("mapa.shared::cluster.u32 %0, %1, %2;" : "=r"(rmb[r]) : "r"(mb_sh), "r"(r));
    }

    // gate-compute mapping: warp w: row-group rg=w&3, batch-group bg=w>>2
    const int w = tid >> 5, l = tid & 31;
    const int rg = w & 3, bg = w >> 2;
    const int rr = rg * 32 + l;
    const int grow = rg * 256 + 32 * (int)rank + l;
    const float4* sW4 = (const float4*)sW;

    const float* gin[4];
#pragma unroll
    for (int i = 0; i < 4; ++i)
        gin[i] = g_gates + ((size_t)(dir * NB + bgrp * 8 + bg * 4 + i)) * NT * NG + grow;

    // activation mapping: batch ab = tid>>5, col aj = tid&31
    const int ab = tid >> 5, aj = tid & 31;
    float c_reg = 0.0f;
    float* ghout = g_h + ((size_t)(dir * NB + bgrp * 8 + ab)) * (NT * NH) + 32 * (int)rank + aj;
    // byte offset within hs buffer for this thread's h value (without buffer select)
    const uint32_t h_off = (uint32_t)(ab * 256 + 32 * (int)rank + aj) * 4u;

    int ph0 = 0, ph1 = 0;  // parity trackers for mb[0], mb[1]

    for (int t = 0; t < NT; ++t) {
        const int cur = t & 1, nxt = cur ^ 1;

        // Wait for this step's h exchange (none needed at t=0)
        if (t > 0) {
            if (cur) { MBWAIT_CL(mb_sh + 8, ph1); ph1 ^= 1; }
            else     { MBWAIT_CL(mb_sh,     ph0); ph0 ^= 1; }
            // re-arm the just-flipped mbarrier for its next phase
            if (tid == 0) {
                uint32_t mb = mb_sh + (uint32_t)(cur * 8);
                asm volatile("mbarrier.arrive.expect_tx.shared.b64 _, [%0], %1;"
                             :: "r"(mb), "r"(TXBYTES) : "memory");
            }
        }

        float gi0 = gin[0][(size_t)t * NG];
        float gi1 = gin[1][(size_t)t * NG];
        float gi2 = gin[2][(size_t)t * NG];
        float gi3 = gin[3][(size_t)t * NG];

        float acc0 = 0.f, acc1 = 0.f, acc2v = 0.f, acc3 = 0.f;
        if (t > 0) {
            const float4* h0 = (const float4*)(hs + cur * 2048 + (bg * 4 + 0) * 256);
            const float4* h1 = (const float4*)(hs + cur * 2048 + (bg * 4 + 1) * 256);
            const float4* h2 = (const float4*)(hs + cur * 2048 + (bg * 4 + 2) * 256);
            const float4* h3 = (const float4*)(hs + cur * 2048 + (bg * 4 + 3) * 256);
#pragma unroll 4
            for (int k4 = 0; k4 < 64; ++k4) {
                float4 wv = sW4[k4 * 128 + rr];
                float4 ha = h0[k4], hb = h1[k4], hc = h2[k4], hd = h3[k4];
                acc0 = fmaf(wv.x, ha.x, acc0); acc0 = fmaf(wv.y, ha.y, acc0);
                acc0 = fmaf(wv.z, ha.z, acc0); acc0 = fmaf(wv.w, ha.w, acc0);
                acc1 = fmaf(wv.x, hb.x, acc1); acc1 = fmaf(wv.y, hb.y, acc1);
                acc1 = fmaf(wv.z, hb.z, acc1); acc1 = fmaf(wv.w, hb.w, acc1);
                acc2v = fmaf(wv.x, hc.x, acc2v); acc2v = fmaf(wv.y, hc.y, acc2v);
                acc2v = fmaf(wv.z, hc.z, acc2v); acc2v = fmaf(wv.w, hc.w, acc2v);
                acc3 = fmaf(wv.x, hd.x, acc3); acc3 = fmaf(wv.y, hd.y, acc3);
                acc3 = fmaf(wv.z, hd.z, acc3); acc3 = fmaf(wv.w, hd.w, acc3);
            }
        }
        gs[(bg * 4 + 0) * 128 + rr] = acc0 + gi0;
        gs[(bg * 4 + 1) * 128 + rr] = acc1 + gi1;
        gs[(bg * 4 + 2) * 128 + rr] = acc2v + gi2;
        gs[(bg * 4 + 3) * 128 + rr] = acc3 + gi3;
        __syncthreads();

        // activation (batch ab, col 32*rank+aj), then broadcast h via st.async
        {
            float iv = sigf(gs[ab * 128 + aj]);
            float fv = sigf(gs[ab * 128 + 32 + aj]);
            float gv = tanhf(gs[ab * 128 + 64 + aj]);
            float ov = sigf(gs[ab * 128 + 96 + aj]);
            c_reg = fv * c_reg + iv * gv;
            float h = ov * tanhf(c_reg);
            ghout[(size_t)t * NH] = h;

            const uint32_t dsto = (uint32_t)(nxt * 2048 * 4) + h_off;
            const uint32_t mbo  = (uint32_t)(nxt * 8);
            const uint32_t hbits = __float_as_uint(h);
#pragma unroll
            for (int r = 0; r < 8; ++r) {
                asm volatile(
                    "st.async.shared::cluster.mbarrier::complete_tx::bytes.b32 [%0], %1, [%2];"
                    :: "r"(rhs[r] + dsto), "r"(hbits), "r"(rmb[r] + mbo) : "memory");
            }
        }
        // No per-step CTA/cluster barrier: the tx-mbarrier wait at the next
        // loop top provides both data-ready and anti-dependency ordering
        // (every CTA stores only after its reads; phase completes only after
        // ALL 2048 values from ALL CTAs arrived).
    }

    // Drain the final exchange (writes of t=255 target mb[0]) so no CTA exits
    // while st.async traffic targeting it is in flight.
    MBWAIT_CL(mb_sh, ph0);
    asm volatile("barrier.cluster.arrive.aligned;" ::: "memory");
    asm volatile("barrier.cluster.wait.aligned;" ::: "memory");
}

// ---------------------------------------------------------------------------
// Kernel 3: emissions. One warp per (b,t); lane = tag. 4 acc chains.
// ---------------------------------------------------------------------------
__global__ void __launch_bounds__(256) emissions_kernel(
    const int* __restrict__ lens, const float* __restrict__ b_out)
{
    const int item = blockIdx.x * 8 + (threadIdx.x >> 5);
    const int lane = threadIdx.x & 31;
    const int b = item >> 8, t = item & 255;
    const int len = lens[b];
    const int tb = (t < len) ? (len - 1 - t) : t;

    const float* hf = g_h + ((size_t)0 * NB + b) * NT * NH + (size_t)t * NH;
    const float* hb = g_h + ((size_t)1 * NB + b) * NT * NH + (size_t)tb * NH;
    const float* __restrict__ wT = g_wOutT;

    float acc0 = b_out[lane], acc1 = 0.f, acc2 = 0.f, acc3 = 0.f;
#pragma unroll 4
    for (int k16 = 0; k16 < 16; ++k16) {
        float4 ha = *(const float4*)(hf + k16 * 16);
        float4 hbv = *(const float4*)(hf + k16 * 16 + 4);
        float4 hc = *(const float4*)(hf + k16 * 16 + 8);
        float4 hd = *(const float4*)(hf + k16 * 16 + 12);
        const float* w0 = wT + (k16 * 16) * NC + lane;
        acc0 = fmaf(ha.x, w0[0 * NC], acc0);  acc1 = fmaf(ha.y, w0[1 * NC], acc1);
        acc2 = fmaf(ha.z, w0[2 * NC], acc2);  acc3 = fmaf(ha.w, w0[3 * NC], acc3);
        acc0 = fmaf(hbv.x, w0[4 * NC], acc0); acc1 = fmaf(hbv.y, w0[5 * NC], acc1);
        acc2 = fmaf(hbv.z, w0[6 * NC], acc2); acc3 = fmaf(hbv.w, w0[7 * NC], acc3);
        acc0 = fmaf(hc.x, w0[8 * NC], acc0);  acc1 = fmaf(hc.y, w0[9 * NC], acc1);
        acc2 = fmaf(hc.z, w0[10 * NC], acc2); acc3 = fmaf(hc.w, w0[11 * NC], acc3);
        acc0 = fmaf(hd.x, w0[12 * NC], acc0); acc1 = fmaf(hd.y, w0[13 * NC], acc1);
        acc2 = fmaf(hd.z, w0[14 * NC], acc2); acc3 = fmaf(hd.w, w0[15 * NC], acc3);
    }
#pragma unroll 4
    for (int k16 = 0; k16 < 16; ++k16) {
        float4 ha = *(const float4*)(hb + k16 * 16);
        float4 hbv = *(const float4*)(hb + k16 * 16 + 4);
        float4 hc = *(const float4*)(hb + k16 * 16 + 8);
        float4 hd = *(const float4*)(hb + k16 * 16 + 12);
        const float* w0 = wT + (NH + k16 * 16) * NC + lane;
        acc0 = fmaf(ha.x, w0[0 * NC], acc0);  acc1 = fmaf(ha.y, w0[1 * NC], acc1);
        acc2 = fmaf(ha.z, w0[2 * NC], acc2);  acc3 = fmaf(ha.w, w0[3 * NC], acc3);
        acc0 = fmaf(hbv.x, w0[4 * NC], acc0); acc1 = fmaf(hbv.y, w0[5 * NC], acc1);
        acc2 = fmaf(hbv.z, w0[6 * NC], acc2); acc3 = fmaf(hbv.w, w0[7 * NC], acc3);
        acc0 = fmaf(hc.x, w0[8 * NC], acc0);  acc1 = fmaf(hc.y, w0[9 * NC], acc1);
        acc2 = fmaf(hc.z, w0[10 * NC], acc2); acc3 = fmaf(hc.w, w0[11 * NC], acc3);
        acc0 = fmaf(hd.x, w0[12 * NC], acc0); acc1 = fmaf(hd.y, w0[13 * NC], acc1);
        acc2 = fmaf(hd.z, w0[14 * NC], acc2); acc3 = fmaf(hd.w, w0[15 * NC], acc3);
    }
    g_em[(size_t)item * NC + lane] = (acc0 + acc1) + (acc2 + acc3);
}

// ---------------------------------------------------------------------------
// Kernel 4: Viterbi decode. One warp per batch element; lane = tag.
// ---------------------------------------------------------------------------
__global__ void __launch_bounds__(32) viterbi_kernel(
    const int* __restrict__ lens,
    const float* __restrict__ start_trans, const float* __restrict__ end_trans,
    const float* __restrict__ trans, float* __restrict__ out)
{
    const int b = blockIdx.x;
    const int lane = threadIdx.x;

    __shared__ int hist[NT - 1][NC];

    float tr[NC];
#pragma unroll
    for (int cp = 0; cp < NC; ++cp) tr[cp] = trans[cp * NC + lane];

    const int len = lens[b];
    const float* emp = g_em + (size_t)b * NT * NC;
    float score = start_trans[lane] + emp[lane];
    float em_next = emp[NC + lane];

    for (int t = 1; t < NT; ++t) {
        float best = -1e30f;
        int bp = 0;
#pragma unroll
        for (int cp = 0; cp < NC; ++cp) {
            float sc = __shfl_sync(0xffffffffu, score, cp) + tr[cp];
            if (sc > best) { best = sc; bp = cp; }
        }
        hist[t - 1][lane] = bp;
        float em_cur = em_next;
        if (t + 1 < NT) em_next = emp[(t + 1) * NC + lane];
        if (t < len) score = best + em_cur;
    }
    score += end_trans[lane];

    float v = score;
    int idx = lane;
#pragma unroll
    for (int off = 16; off; off >>= 1) {
        float v2 = __shfl_xor_sync(0xffffffffu, v, off);
        int i2 = __shfl_xor_sync(0xffffffffu, idx, off);
        if (v2 > v || (v2 == v && i2 < idx)) { v = v2; idx = i2; }
    }

    if (lane == 0) {
        out[NB * NT + b] = v;
        int tag = idx;
        out[(size_t)b * NT + (NT - 1)] = (float)tag;
        for (int t = NT - 2; t >= 0; --t) {
            if (t < len - 1) tag = hist[t][tag];
            out[(size_t)b * NT + t] = (float)tag;
        }
    }
}

// ---------------------------------------------------------------------------
extern "C" void kernel_launch(void* const* d_in, const int* in_sizes, int n_in,
                              void* d_out, int out_size)
{
    const int*   sent   = (const int*)d_in[0];
    const int*   lens   = (const int*)d_in[1];
    const float* emb    = (const float*)d_in[2];
    const float* w_ih_f = (const float*)d_in[3];
    const float* w_hh_f = (const float*)d_in[4];
    const float* b_ih_f = (const float*)d_in[5];
    const float* b_hh_f = (const float*)d_in[6];
    const float* w_ih_b = (const float*)d_in[7];
    const float* w_hh_b = (const float*)d_in[8];
    const float* b_ih_b = (const float*)d_in[9];
    const float* b_hh_b = (const float*)d_in[10];
    const float* w_out  = (const float*)d_in[11];
    const float* b_out  = (const float*)d_in[12];
    const float* start_trans = (const float*)d_in[13];
    const float* end_trans   = (const float*)d_in[14];
    const float* trans       = (const float*)d_in[15];
    float* out = (float*)d_out;

    cudaFuncSetAttribute(lstm_cluster_kernel,
                         cudaFuncAttributeMaxDynamicSharedMemorySize, LSMEM_BYTES);

    dim3 tb(32, 8);
    transpose_wout_kernel<<<dim3((2 * NH) / 32, 1, 1), tb>>>(w_out);

    dim3 g1(128, 16);
    input_proj_kernel<<<g1, 256>>>(sent, lens, emb,
                                   w_ih_f, b_ih_f, b_hh_f,
                                   w_ih_b, b_ih_b, b_hh_b);
    lstm_cluster_kernel<<<128, 256, LSMEM_BYTES>>>(w_hh_f, w_hh_b);
    emissions_kernel<<<NB * NT / 8, 256>>>(lens, b_out);
    viterbi_kernel<<<NB, 32>>>(lens, start_trans, end_trans, trans, out);
}

// round 9
// speedup vs baseline: 1.3997x; 1.3041x over previous
#include <cuda_runtime.h>
#include <stdint.h>
#include <math.h>

// Problem constants
constexpr int NB = 64;    // batch
constexpr int NT = 256;   // time
constexpr int ND = 256;   // embed dim
constexpr int NH = 256;   // hidden per direction
constexpr int NC = 32;    // tags
constexpr int NG = 1024;  // 4*NH gate rows

// Scratch (static device allocations; no cudaMalloc allowed)
__device__ __align__(16) float g_gates[(size_t)2 * NB * NT * NG];
__device__ __align__(16) float g_h[(size_t)2 * NB * NT * NH];
__device__ __align__(16) float g_em[(size_t)NB * NT * NC];
__device__ __align__(16) float g_wOutT[(size_t)2 * NH * NC];

__device__ __forceinline__ float sigf(float x) { return 1.0f / (1.0f + __expf(-x)); }

// Packed fp32x2 helpers (Blackwell FFMA2; bit-exact fp32 FMA semantics per lane)
__device__ __forceinline__ void fma2(unsigned long long& d, unsigned long long a,
                                     unsigned long long b) {
    asm("fma.rn.f32x2 %0, %1, %2, %0;" : "+l"(d) : "l"(a), "l"(b));
}
__device__ __forceinline__ float lo2(unsigned long long v) {
    return __uint_as_float((unsigned)(v & 0xffffffffull));
}
__device__ __forceinline__ float hi2(unsigned long long v) {
    return __uint_as_float((unsigned)(v >> 32));
}

// ---------------------------------------------------------------------------
// Kernel 0: transpose w_out [32][512] -> g_wOutT[512][32]
// ---------------------------------------------------------------------------
__global__ void transpose_wout_kernel(const float* __restrict__ w)
{
    __shared__ float tile[32][33];
    const int k0 = blockIdx.x * 32;
    const int tx = threadIdx.x, ty = threadIdx.y;
#pragma unroll
    for (int i = 0; i < 32; i += 8)
        tile[ty + i][tx] = w[(size_t)(ty + i) * (2 * NH) + k0 + tx];
    __syncthreads();
#pragma unroll
    for (int i = 0; i < 32; i += 8)
        g_wOutT[(size_t)(k0 + ty + i) * NC + tx] = tile[tx][ty + i];
}

// ---------------------------------------------------------------------------
// Kernel 1: embedding gather + input projection (both directions).
// SGEMM: BM=128, BN=128, BK=16, 256 threads, 8x8 microtile.
// Double-buffered smem (ping-pong), 1 __syncthreads per k-tile.
// ---------------------------------------------------------------------------
__global__ void __launch_bounds__(256) input_proj_kernel(
    const int* __restrict__ sent, const int* __restrict__ lens,
    const float* __restrict__ emb,
    const float* __restrict__ w_f, const float* __restrict__ bi_f, const float* __restrict__ bh_f,
    const float* __restrict__ w_b, const float* __restrict__ bi_b, const float* __restrict__ bh_b)
{
    const int dir = blockIdx.y >> 3;
    const int n0  = (blockIdx.y & 7) * 128;
    const int m0  = blockIdx.x * 128;

    const float* __restrict__ W  = dir ? w_b  : w_f;
    const float* __restrict__ BI = dir ? bi_b : bi_f;
    const float* __restrict__ BH = dir ? bh_b : bh_f;

    __shared__ __align__(16) float As[2][16][128];
    __shared__ __align__(16) float Bs[2][16][128];
    __shared__ int toks[128];

    const int tid = threadIdx.x;
    if (tid < 128) {
        int m = m0 + tid;
        int b = m >> 8, t = m & 255;
        int ts = t;
        if (dir) { int len = lens[b]; if (t < len) ts = len - 1 - t; }
        toks[tid] = sent[b * NT + ts];
    }
    __syncthreads();

    const int lrow2 = tid >> 2;
    const int lane4 = tid & 3;
    const int row0 = lrow2, row1 = lrow2 + 64;
    const float* arow0 = emb + (size_t)toks[row0] * ND + lane4 * 4;
    const float* arow1 = emb + (size_t)toks[row1] * ND + lane4 * 4;
    const float* brow0 = W + (size_t)(n0 + row0) * ND + lane4 * 4;
    const float* brow1 = W + (size_t)(n0 + row1) * ND + lane4 * 4;

    const int tx = tid & 15, ty = tid >> 4;

    float acc[8][8];
#pragma unroll
    for (int i = 0; i < 8; i++)
#pragma unroll
        for (int j = 0; j < 8; j++) acc[i][j] = 0.0f;

    // prologue: tile 0 -> buffer 0
    {
        float4 a0 = *(const float4*)(arow0);
        float4 a1 = *(const float4*)(arow1);
        float4 b0 = *(const float4*)(brow0);
        float4 b1 = *(const float4*)(brow1);
        As[0][lane4 * 4 + 0][row0] = a0.x; As[0][lane4 * 4 + 1][row0] = a0.y;
        As[0][lane4 * 4 + 2][row0] = a0.z; As[0][lane4 * 4 + 3][row0] = a0.w;
        As[0][lane4 * 4 + 0][row1] = a1.x; As[0][lane4 * 4 + 1][row1] = a1.y;
        As[0][lane4 * 4 + 2][row1] = a1.z; As[0][lane4 * 4 + 3][row1] = a1.w;
        Bs[0][lane4 * 4 + 0][row0] = b0.x; Bs[0][lane4 * 4 + 1][row0] = b0.y;
        Bs[0][lane4 * 4 + 2][row0] = b0.z; Bs[0][lane4 * 4 + 3][row0] = b0.w;
        Bs[0][lane4 * 4 + 0][row1] = b1.x; Bs[0][lane4 * 4 + 1][row1] = b1.y;
        Bs[0][lane4 * 4 + 2][row1] = b1.z; Bs[0][lane4 * 4 + 3][row1] = b1.w;
    }
    __syncthreads();

    for (int it = 0; it < 16; ++it) {
        const int cb = it & 1, nb = cb ^ 1;
        float4 pa0, pa1, pb0, pb1;
        const bool pf = (it < 15);
        if (pf) {
            int kk = (it + 1) * 16;
            pa0 = *(const float4*)(arow0 + kk);
            pa1 = *(const float4*)(arow1 + kk);
            pb0 = *(const float4*)(brow0 + kk);
            pb1 = *(const float4*)(brow1 + kk);
        }
#pragma unroll
        for (int k = 0; k < 16; ++k) {
            float4 av0 = *(const float4*)&As[cb][k][ty * 8];
            float4 av1 = *(const float4*)&As[cb][k][ty * 8 + 4];
            float4 bv0 = *(const float4*)&Bs[cb][k][tx * 8];
            float4 bv1 = *(const float4*)&Bs[cb][k][tx * 8 + 4];
            float a[8] = {av0.x, av0.y, av0.z, av0.w, av1.x, av1.y, av1.z, av1.w};
            float bb[8] = {bv0.x, bv0.y, bv0.z, bv0.w, bv1.x, bv1.y, bv1.z, bv1.w};
#pragma unroll
            for (int i = 0; i < 8; i++)
#pragma unroll
                for (int j = 0; j < 8; j++) acc[i][j] = fmaf(a[i], bb[j], acc[i][j]);
        }
        if (pf) {
            As[nb][lane4 * 4 + 0][row0] = pa0.x; As[nb][lane4 * 4 + 1][row0] = pa0.y;
            As[nb][lane4 * 4 + 2][row0] = pa0.z; As[nb][lane4 * 4 + 3][row0] = pa0.w;
            As[nb][lane4 * 4 + 0][row1] = pa1.x; As[nb][lane4 * 4 + 1][row1] = pa1.y;
            As[nb][lane4 * 4 + 2][row1] = pa1.z; As[nb][lane4 * 4 + 3][row1] = pa1.w;
            Bs[nb][lane4 * 4 + 0][row0] = pb0.x; Bs[nb][lane4 * 4 + 1][row0] = pb0.y;
            Bs[nb][lane4 * 4 + 2][row0] = pb0.z; Bs[nb][lane4 * 4 + 3][row0] = pb0.w;
            Bs[nb][lane4 * 4 + 0][row1] = pb1.x; Bs[nb][lane4 * 4 + 1][row1] = pb1.y;
            Bs[nb][lane4 * 4 + 2][row1] = pb1.z; Bs[nb][lane4 * 4 + 3][row1] = pb1.w;
        }
        __syncthreads();
    }

    float bias[8];
#pragma unroll
    for (int j = 0; j < 8; j++) {
        int n = n0 + tx * 8 + j;
        bias[j] = BI[n] + BH[n];
    }
#pragma unroll
    for (int i = 0; i < 8; i++) {
        int m = m0 + ty * 8 + i;
        float* o = g_gates + ((size_t)dir * (NB * NT) + m) * NG + n0 + tx * 8;
        float4 s0, s1;
        s0.x = acc[i][0] + bias[0]; s0.y = acc[i][1] + bias[1];
        s0.z = acc[i][2] + bias[2]; s0.w = acc[i][3] + bias[3];
        s1.x = acc[i][4] + bias[4]; s1.y = acc[i][5] + bias[5];
        s1.z = acc[i][6] + bias[6]; s1.w = acc[i][7] + bias[7];
        *(float4*)o = s0;
        *(float4*)(o + 4) = s1;
    }
}

// ---------------------------------------------------------------------------
// Kernel 2: cluster LSTM — weights in REGISTERS (packed f32x2), tx-mbarrier
// h-exchange (no barrier.cluster in loop).
// 128 CTAs = 16 clusters x 8. Cluster = (dir, batch-group of 8).
// CTA rank r owns h-cols [32r,32r+32) -> 128 gate rows. Thread = (row, k-half):
// 64 packed weight regs, 8 packed accumulators (8 batches).
// ---------------------------------------------------------------------------
constexpr int LS_H  = 4096;                  // hs double buffer floats
constexpr int LS_G  = 2048;                  // gs partials: [2 kh][8 b][128 rows]
constexpr int LS_MBAR_OFF = (LS_H + LS_G) * 4;
constexpr int LSMEM_BYTES = LS_MBAR_OFF + 16;
constexpr unsigned TXBYTES = 2048u * 4u;     // per-phase expected bytes

#define MBWAIT_CL(mbar, par) do {                                              \
    asm volatile(                                                              \
        "{\n\t.reg .pred P1;\n\t"                                              \
        "WL%=:\n\t"                                                            \
        "mbarrier.try_wait.parity.acquire.cluster.shared::cta.b64 P1, [%0], %1, 0x989680;\n\t" \
        "@P1 bra WD%=;\n\t"                                                    \
        "bra WL%=;\n\t"                                                        \
        "WD%=:\n\t}"                                                           \
        :: "r"(mbar), "r"(par) : "memory");                                    \
} while (0)

__global__ void __launch_bounds__(256, 1) __cluster_dims__(8, 1, 1)
lstm_cluster_kernel(const float* __restrict__ w_hh_f, const float* __restrict__ w_hh_b)
{
    extern __shared__ __align__(16) float smem[];
    float* hs = smem;                  // [2][8 batches][256]
    float* gs = smem + LS_H;           // [2 kh][8 batches][128 rows]

    const int tid = threadIdx.x;
    uint32_t rank;
    asm("mov.u32 %0, %%cluster_ctarank;" : "=r"(rank));
    const int cl = blockIdx.x >> 3;
    const int dir = cl & 1;
    const int bgrp = cl >> 1;

    const float* __restrict__ whh = dir ? w_hh_b : w_hh_f;

    // thread mapping: row = tid&127 (gate row within slice), kh = tid>>7
    const int row = tid & 127;
    const int kh  = tid >> 7;
    const int g_global = (row >> 5) * 256 + 32 * (int)rank + (row & 31);

    // ---- weights into registers: 64 packed f32x2 (k-pairs of this k-half)
    unsigned long long w2[64];
    {
        const float* wsrc = whh + (size_t)g_global * NH + kh * 128;
#pragma unroll
        for (int j = 0; j < 64; ++j)
            w2[j] = *(const unsigned long long*)(wsrc + 2 * j);
    }

    // SMEM u32 addresses
    uint32_t smem_base;
    asm("{ .reg .u64 t; cvta.to.shared.u64 t, %1; cvt.u32.u64 %0, t; }"
        : "=r"(smem_base) : "l"(smem));
    const uint32_t hs_sh = smem_base;
    const uint32_t mb_sh = smem_base + (uint32_t)LS_MBAR_OFF;

    if (tid == 0) {
        asm volatile("mbarrier.init.shared.b64 [%0], 1;" :: "r"(mb_sh) : "memory");
        asm volatile("mbarrier.init.shared.b64 [%0], 1;" :: "r"(mb_sh + 8) : "memory");
        asm volatile("mbarrier.arrive.expect_tx.shared.b64 _, [%0], %1;"
                     :: "r"(mb_sh), "r"(TXBYTES) : "memory");
        asm volatile("mbarrier.arrive.expect_tx.shared.b64 _, [%0], %1;"
                     :: "r"(mb_sh + 8), "r"(TXBYTES) : "memory");
    }
    __syncthreads();

    // cluster-wide: mbarrier inits visible before any st.async arrives
    asm volatile("barrier.cluster.arrive.aligned;" ::: "memory");
    asm volatile("barrier.cluster.wait.aligned;" ::: "memory");

    uint32_t rhs[8], rmb[8];
#pragma unroll
    for (int r = 0; r < 8; ++r) {
        asm("mapa.shared::cluster.u32 %0, %1, %2;" : "=r"(rhs[r]) : "r"(hs_sh), "r"(r));
        asm("mapa.shared::cluster.u32 %0, %1, %2;" : "=r"(rmb[r]) : "r"(mb_sh), "r"(r));
    }

    // gin base: batch b at base + b*NT*NG (loaded by kh==0 threads only)
    const float* ginbase = g_gates + ((size_t)(dir * NB + bgrp * 8)) * NT * NG + g_global;

    // activation mapping: batch ab = tid>>5, col aj = tid&31
    const int ab = tid >> 5, aj = tid & 31;
    float c_reg = 0.0f;
    float* ghout = g_h + ((size_t)(dir * NB + bgrp * 8 + ab)) * (NT * NH) + 32 * (int)rank + aj;
    const uint32_t h_off = (uint32_t)(ab * 256 + 32 * (int)rank + aj) * 4u;

    int ph0 = 0, ph1 = 0;

    for (int t = 0; t < NT; ++t) {
        const int cur = t & 1, nxt = cur ^ 1;

        if (t > 0) {
            if (cur) { MBWAIT_CL(mb_sh + 8, ph1); ph1 ^= 1; }
            else     { MBWAIT_CL(mb_sh,     ph0); ph0 ^= 1; }
            if (tid == 0) {
                uint32_t mb = mb_sh + (uint32_t)(cur * 8);
                asm volatile("mbarrier.arrive.expect_tx.shared.b64 _, [%0], %1;"
                             :: "r"(mb), "r"(TXBYTES) : "memory");
            }
        }

        // prefetch input-projected gate rows (kh0 threads; 8 batches)
        float gi[8];
        if (kh == 0) {
#pragma unroll
            for (int b = 0; b < 8; ++b)
                gi[b] = ginbase[(size_t)t * NG + (size_t)b * NT * NG];
        }

        unsigned long long acc2[8];
#pragma unroll
        for (int b = 0; b < 8; ++b) acc2[b] = 0ull;

        if (t > 0) {
            // h for this k-half; broadcast LDS.128 = 2 packed pairs
            const ulonglong2* hb = (const ulonglong2*)(hs + cur * 2048 + kh * 128);
#pragma unroll
            for (int k4 = 0; k4 < 32; ++k4) {
#pragma unroll
                for (int b = 0; b < 8; ++b) {
                    ulonglong2 hv = hb[b * 64 + k4];
                    fma2(acc2[b], w2[2 * k4], hv.x);
                    fma2(acc2[b], w2[2 * k4 + 1], hv.y);
                }
            }
        }

        // store partials
#pragma unroll
        for (int b = 0; b < 8; ++b) {
            float p = lo2(acc2[b]) + hi2(acc2[b]);
            if (kh == 0) p += gi[b];
            gs[(kh * 8 + b) * 128 + row] = p;
        }
        __syncthreads();

        // activation (batch ab, col 32*rank+aj) and h broadcast via st.async
        {
            float pi = gs[(0 * 8 + ab) * 128 + 0 * 32 + aj] + gs[(8 + ab) * 128 + 0 * 32 + aj];
            float pf = gs[(0 * 8 + ab) * 128 + 1 * 32 + aj] + gs[(8 + ab) * 128 + 1 * 32 + aj];
            float pg = gs[(0 * 8 + ab) * 128 + 2 * 32 + aj] + gs[(8 + ab) * 128 + 2 * 32 + aj];
            float po = gs[(0 * 8 + ab) * 128 + 3 * 32 + aj] + gs[(8 + ab) * 128 + 3 * 32 + aj];
            float iv = sigf(pi);
            float fv = sigf(pf);
            float gv = tanhf(pg);
            float ov = sigf(po);
            c_reg = fv * c_reg + iv * gv;
            float h = ov * tanhf(c_reg);
            ghout[(size_t)t * NH] = h;

            const uint32_t dsto = (uint32_t)(nxt * 2048 * 4) + h_off;
            const uint32_t mbo  = (uint32_t)(nxt * 8);
            const uint32_t hbits = __float_as_uint(h);
#pragma unroll
            for (int r = 0; r < 8; ++r) {
                asm volatile(
                    "st.async.shared::cluster.mbarrier::complete_tx::bytes.b32 [%0], %1, [%2];"
                    :: "r"(rhs[r] + dsto), "r"(hbits), "r"(rmb[r] + mbo) : "memory");
            }
        }
        // no per-step cluster barrier: mbarrier tx-wait at next loop top
        // provides data-ready and anti-dependency ordering (proved in R8).
    }

    // drain final exchange so no CTA exits with in-flight st.async targeting it
    MBWAIT_CL(mb_sh, ph0);
    asm volatile("barrier.cluster.arrive.aligned;" ::: "memory");
    asm volatile("barrier.cluster.wait.aligned;" ::: "memory");
}

// ---------------------------------------------------------------------------
// Kernel 3: emissions. One warp per (b,t); lane = tag. 4 acc chains.
// ---------------------------------------------------------------------------
__global__ void __launch_bounds__(256) emissions_kernel(
    const int* __restrict__ lens, const float* __restrict__ b_out)
{
    const int item = blockIdx.x * 8 + (threadIdx.x >> 5);
    const int lane = threadIdx.x & 31;
    const int b = item >> 8, t = item & 255;
    const int len = lens[b];
    const int tb = (t < len) ? (len - 1 - t) : t;

    const float* hf = g_h + ((size_t)0 * NB + b) * NT * NH + (size_t)t * NH;
    const float* hb = g_h + ((size_t)1 * NB + b) * NT * NH + (size_t)tb * NH;
    const float* __restrict__ wT = g_wOutT;

    float acc0 = b_out[lane], acc1 = 0.f, acc2 = 0.f, acc3 = 0.f;
#pragma unroll 4
    for (int k16 = 0; k16 < 16; ++k16) {
        float4 ha = *(const float4*)(hf + k16 * 16);
        float4 hbv = *(const float4*)(hf + k16 * 16 + 4);
        float4 hc = *(const float4*)(hf + k16 * 16 + 8);
        float4 hd = *(const float4*)(hf + k16 * 16 + 12);
        const float* w0 = wT + (k16 * 16) * NC + lane;
        acc0 = fmaf(ha.x, w0[0 * NC], acc0);  acc1 = fmaf(ha.y, w0[1 * NC], acc1);
        acc2 = fmaf(ha.z, w0[2 * NC], acc2);  acc3 = fmaf(ha.w, w0[3 * NC], acc3);
        acc0 = fmaf(hbv.x, w0[4 * NC], acc0); acc1 = fmaf(hbv.y, w0[5 * NC], acc1);
        acc2 = fmaf(hbv.z, w0[6 * NC], acc2); acc3 = fmaf(hbv.w, w0[7 * NC], acc3);
        acc0 = fmaf(hc.x, w0[8 * NC], acc0);  acc1 = fmaf(hc.y, w0[9 * NC], acc1);
        acc2 = fmaf(hc.z, w0[10 * NC], acc2); acc3 = fmaf(hc.w, w0[11 * NC], acc3);
        acc0 = fmaf(hd.x, w0[12 * NC], acc0); acc1 = fmaf(hd.y, w0[13 * NC], acc1);
        acc2 = fmaf(hd.z, w0[14 * NC], acc2); acc3 = fmaf(hd.w, w0[15 * NC], acc3);
    }
#pragma unroll 4
    for (int k16 = 0; k16 < 16; ++k16) {
        float4 ha = *(const float4*)(hb + k16 * 16);
        float4 hbv = *(const float4*)(hb + k16 * 16 + 4);
        float4 hc = *(const float4*)(hb + k16 * 16 + 8);
        float4 hd = *(const float4*)(hb + k16 * 16 + 12);
        const float* w0 = wT + (NH + k16 * 16) * NC + lane;
        acc0 = fmaf(ha.x, w0[0 * NC], acc0);  acc1 = fmaf(ha.y, w0[1 * NC], acc1);
        acc2 = fmaf(ha.z, w0[2 * NC], acc2);  acc3 = fmaf(ha.w, w0[3 * NC], acc3);
        acc0 = fmaf(hbv.x, w0[4 * NC], acc0); acc1 = fmaf(hbv.y, w0[5 * NC], acc1);
        acc2 = fmaf(hbv.z, w0[6 * NC], acc2); acc3 = fmaf(hbv.w, w0[7 * NC], acc3);
        acc0 = fmaf(hc.x, w0[8 * NC], acc0);  acc1 = fmaf(hc.y, w0[9 * NC], acc1);
        acc2 = fmaf(hc.z, w0[10 * NC], acc2); acc3 = fmaf(hc.w, w0[11 * NC], acc3);
        acc0 = fmaf(hd.x, w0[12 * NC], acc0); acc1 = fmaf(hd.y, w0[13 * NC], acc1);
        acc2 = fmaf(hd.z, w0[14 * NC], acc2); acc3 = fmaf(hd.w, w0[15 * NC], acc3);
    }
    g_em[(size_t)item * NC + lane] = (acc0 + acc1) + (acc2 + acc3);
}

// ---------------------------------------------------------------------------
// Kernel 4: Viterbi decode. One warp per batch element; lane = tag.
// ---------------------------------------------------------------------------
__global__ void __launch_bounds__(32) viterbi_kernel(
    const int* __restrict__ lens,
    const float* __restrict__ start_trans, const float* __restrict__ end_trans,
    const float* __restrict__ trans, float* __restrict__ out)
{
    const int b = blockIdx.x;
    const int lane = threadIdx.x;

    __shared__ int hist[NT - 1][NC];

    float tr[NC];
#pragma unroll
    for (int cp = 0; cp < NC; ++cp) tr[cp] = trans[cp * NC + lane];

    const int len = lens[b];
    const float* emp = g_em + (size_t)b * NT * NC;
    float score = start_trans[lane] + emp[lane];
    float em_next = emp[NC + lane];

    for (int t = 1; t < NT; ++t) {
        float best = -1e30f;
        int bp = 0;
#pragma unroll
        for (int cp = 0; cp < NC; ++cp) {
            float sc = __shfl_sync(0xffffffffu, score, cp) + tr[cp];
            if (sc > best) { best = sc; bp = cp; }
        }
        hist[t - 1][lane] = bp;
        float em_cur = em_next;
        if (t + 1 < NT) em_next = emp[(t + 1) * NC + lane];
        if (t < len) score = best + em_cur;
    }
    score += end_trans[lane];

    float v = score;
    int idx = lane;
#pragma unroll
    for (int off = 16; off; off >>= 1) {
        float v2 = __shfl_xor_sync(0xffffffffu, v, off);
        int i2 = __shfl_xor_sync(0xffffffffu, idx, off);
        if (v2 > v || (v2 == v && i2 < idx)) { v = v2; idx = i2; }
    }

    if (lane == 0) {
        out[NB * NT + b] = v;
        int tag = idx;
        out[(size_t)b * NT + (NT - 1)] = (float)tag;
        for (int t = NT - 2; t >= 0; --t) {
            if (t < len - 1) tag = hist[t][tag];
            out[(size_t)b * NT + t] = (float)tag;
        }
    }
}

// ---------------------------------------------------------------------------
extern "C" void kernel_launch(void* const* d_in, const int* in_sizes, int n_in,
                              void* d_out, int out_size)
{
    const int*   sent   = (const int*)d_in[0];
    const int*   lens   = (const int*)d_in[1];
    const float* emb    = (const float*)d_in[2];
    const float* w_ih_f = (const float*)d_in[3];
    const float* w_hh_f = (const float*)d_in[4];
    const float* b_ih_f = (const float*)d_in[5];
    const float* b_hh_f = (const float*)d_in[6];
    const float* w_ih_b = (const float*)d_in[7];
    const float* w_hh_b = (const float*)d_in[8];
    const float* b_ih_b = (const float*)d_in[9];
    const float* b_hh_b = (const float*)d_in[10];
    const float* w_out  = (const float*)d_in[11];
    const float* b_out  = (const float*)d_in[12];
    const float* start_trans = (const float*)d_in[13];
    const float* end_trans   = (const float*)d_in[14];
    const float* trans       = (const float*)d_in[15];
    float* out = (float*)d_out;

    cudaFuncSetAttribute(lstm_cluster_kernel,
                         cudaFuncAttributeMaxDynamicSharedMemorySize, LSMEM_BYTES);

    dim3 tb(32, 8);
    transpose_wout_kernel<<<dim3((2 * NH) / 32, 1, 1), tb>>>(w_out);

    dim3 g1(128, 16);
    input_proj_kernel<<<g1, 256>>>(sent, lens, emb,
                                   w_ih_f, b_ih_f, b_hh_f,
                                   w_ih_b, b_ih_b, b_hh_b);
    lstm_cluster_kernel<<<128, 256, LSMEM_BYTES>>>(w_hh_f, w_hh_b);
    emissions_kernel<<<NB * NT / 8, 256>>>(lens, b_out);
    viterbi_kernel<<<NB, 32>>>(lens, start_trans, end_trans, trans, out);
}

// round 10
// speedup vs baseline: 1.4478x; 1.0344x over previous
#include <cuda_runtime.h>
#include <stdint.h>
#include <math.h>

// Problem constants
constexpr int NB = 64;    // batch
constexpr int NT = 256;   // time
constexpr int ND = 256;   // embed dim
constexpr int NH = 256;   // hidden per direction
constexpr int NC = 32;    // tags
constexpr int NG = 1024;  // 4*NH gate rows

// Scratch (static device allocations; no cudaMalloc allowed)
__device__ __align__(16) float g_gates[(size_t)2 * NB * NT * NG];
__device__ __align__(16) float g_h[(size_t)2 * NB * NT * NH];
__device__ __align__(16) float g_em[(size_t)NB * NT * NC];
__device__ __align__(16) float g_wOutT[(size_t)2 * NH * NC];

__device__ __forceinline__ float sigf(float x) { return 1.0f / (1.0f + __expf(-x)); }

// Packed fp32x2 helpers (Blackwell FFMA2; bit-exact fp32 FMA semantics per lane)
__device__ __forceinline__ void fma2(unsigned long long& d, unsigned long long a,
                                     unsigned long long b) {
    asm("fma.rn.f32x2 %0, %1, %2, %0;" : "+l"(d) : "l"(a), "l"(b));
}
__device__ __forceinline__ float lo2(unsigned long long v) {
    return __uint_as_float((unsigned)(v & 0xffffffffull));
}
__device__ __forceinline__ float hi2(unsigned long long v) {
    return __uint_as_float((unsigned)(v >> 32));
}

// ---------------------------------------------------------------------------
// Kernel 0: transpose w_out [32][512] -> g_wOutT[512][32]
// ---------------------------------------------------------------------------
__global__ void transpose_wout_kernel(const float* __restrict__ w)
{
    __shared__ float tile[32][33];
    const int k0 = blockIdx.x * 32;
    const int tx = threadIdx.x, ty = threadIdx.y;
#pragma unroll
    for (int i = 0; i < 32; i += 8)
        tile[ty + i][tx] = w[(size_t)(ty + i) * (2 * NH) + k0 + tx];
    __syncthreads();
#pragma unroll
    for (int i = 0; i < 32; i += 8)
        g_wOutT[(size_t)(k0 + ty + i) * NC + tx] = tile[tx][ty + i];
}

// ---------------------------------------------------------------------------
// Kernel 1: embedding gather + input projection (both directions).
// SGEMM: BM=128, BN=128, BK=16, 256 threads, 8x8 microtile.
// Double-buffered smem (ping-pong), 1 __syncthreads per k-tile.
// ---------------------------------------------------------------------------
__global__ void __launch_bounds__(256) input_proj_kernel(
    const int* __restrict__ sent, const int* __restrict__ lens,
    const float* __restrict__ emb,
    const float* __restrict__ w_f, const float* __restrict__ bi_f, const float* __restrict__ bh_f,
    const float* __restrict__ w_b, const float* __restrict__ bi_b, const float* __restrict__ bh_b)
{
    const int dir = blockIdx.y >> 3;
    const int n0  = (blockIdx.y & 7) * 128;
    const int m0  = blockIdx.x * 128;

    const float* __restrict__ W  = dir ? w_b  : w_f;
    const float* __restrict__ BI = dir ? bi_b : bi_f;
    const float* __restrict__ BH = dir ? bh_b : bh_f;

    __shared__ __align__(16) float As[2][16][128];
    __shared__ __align__(16) float Bs[2][16][128];
    __shared__ int toks[128];

    const int tid = threadIdx.x;
    if (tid < 128) {
        int m = m0 + tid;
        int b = m >> 8, t = m & 255;
        int ts = t;
        if (dir) { int len = lens[b]; if (t < len) ts = len - 1 - t; }
        toks[tid] = sent[b * NT + ts];
    }
    __syncthreads();

    const int lrow2 = tid >> 2;
    const int lane4 = tid & 3;
    const int row0 = lrow2, row1 = lrow2 + 64;
    const float* arow0 = emb + (size_t)toks[row0] * ND + lane4 * 4;
    const float* arow1 = emb + (size_t)toks[row1] * ND + lane4 * 4;
    const float* brow0 = W + (size_t)(n0 + row0) * ND + lane4 * 4;
    const float* brow1 = W + (size_t)(n0 + row1) * ND + lane4 * 4;

    const int tx = tid & 15, ty = tid >> 4;

    float acc[8][8];
#pragma unroll
    for (int i = 0; i < 8; i++)
#pragma unroll
        for (int j = 0; j < 8; j++) acc[i][j] = 0.0f;

    // prologue: tile 0 -> buffer 0
    {
        float4 a0 = *(const float4*)(arow0);
        float4 a1 = *(const float4*)(arow1);
        float4 b0 = *(const float4*)(brow0);
        float4 b1 = *(const float4*)(brow1);
        As[0][lane4 * 4 + 0][row0] = a0.x; As[0][lane4 * 4 + 1][row0] = a0.y;
        As[0][lane4 * 4 + 2][row0] = a0.z; As[0][lane4 * 4 + 3][row0] = a0.w;
        As[0][lane4 * 4 + 0][row1] = a1.x; As[0][lane4 * 4 + 1][row1] = a1.y;
        As[0][lane4 * 4 + 2][row1] = a1.z; As[0][lane4 * 4 + 3][row1] = a1.w;
        Bs[0][lane4 * 4 + 0][row0] = b0.x; Bs[0][lane4 * 4 + 1][row0] = b0.y;
        Bs[0][lane4 * 4 + 2][row0] = b0.z; Bs[0][lane4 * 4 + 3][row0] = b0.w;
        Bs[0][lane4 * 4 + 0][row1] = b1.x; Bs[0][lane4 * 4 + 1][row1] = b1.y;
        Bs[0][lane4 * 4 + 2][row1] = b1.z; Bs[0][lane4 * 4 + 3][row1] = b1.w;
    }
    __syncthreads();

    for (int it = 0; it < 16; ++it) {
        const int cb = it & 1, nb = cb ^ 1;
        float4 pa0, pa1, pb0, pb1;
        const bool pf = (it < 15);
        if (pf) {
            int kk = (it + 1) * 16;
            pa0 = *(const float4*)(arow0 + kk);
            pa1 = *(const float4*)(arow1 + kk);
            pb0 = *(const float4*)(brow0 + kk);
            pb1 = *(const float4*)(brow1 + kk);
        }
#pragma unroll
        for (int k = 0; k < 16; ++k) {
            float4 av0 = *(const float4*)&As[cb][k][ty * 8];
            float4 av1 = *(const float4*)&As[cb][k][ty * 8 + 4];
            float4 bv0 = *(const float4*)&Bs[cb][k][tx * 8];
            float4 bv1 = *(const float4*)&Bs[cb][k][tx * 8 + 4];
            float a[8] = {av0.x, av0.y, av0.z, av0.w, av1.x, av1.y, av1.z, av1.w};
            float bb[8] = {bv0.x, bv0.y, bv0.z, bv0.w, bv1.x, bv1.y, bv1.z, bv1.w};
#pragma unroll
            for (int i = 0; i < 8; i++)
#pragma unroll
                for (int j = 0; j < 8; j++) acc[i][j] = fmaf(a[i], bb[j], acc[i][j]);
        }
        if (pf) {
            As[nb][lane4 * 4 + 0][row0] = pa0.x; As[nb][lane4 * 4 + 1][row0] = pa0.y;
            As[nb][lane4 * 4 + 2][row0] = pa0.z; As[nb][lane4 * 4 + 3][row0] = pa0.w;
            As[nb][lane4 * 4 + 0][row1] = pa1.x; As[nb][lane4 * 4 + 1][row1] = pa1.y;
            As[nb][lane4 * 4 + 2][row1] = pa1.z; As[nb][lane4 * 4 + 3][row1] = pa1.w;
            Bs[nb][lane4 * 4 + 0][row0] = pb0.x; Bs[nb][lane4 * 4 + 1][row0] = pb0.y;
            Bs[nb][lane4 * 4 + 2][row0] = pb0.z; Bs[nb][lane4 * 4 + 3][row0] = pb0.w;
            Bs[nb][lane4 * 4 + 0][row1] = pb1.x; Bs[nb][lane4 * 4 + 1][row1] = pb1.y;
            Bs[nb][lane4 * 4 + 2][row1] = pb1.z; Bs[nb][lane4 * 4 + 3][row1] = pb1.w;
        }
        __syncthreads();
    }

    float bias[8];
#pragma unroll
    for (int j = 0; j < 8; j++) {
        int n = n0 + tx * 8 + j;
        bias[j] = BI[n] + BH[n];
    }
#pragma unroll
    for (int i = 0; i < 8; i++) {
        int m = m0 + ty * 8 + i;
        float* o = g_gates + ((size_t)dir * (NB * NT) + m) * NG + n0 + tx * 8;
        float4 s0, s1;
        s0.x = acc[i][0] + bias[0]; s0.y = acc[i][1] + bias[1];
        s0.z = acc[i][2] + bias[2]; s0.w = acc[i][3] + bias[3];
        s1.x = acc[i][4] + bias[4]; s1.y = acc[i][5] + bias[5];
        s1.z = acc[i][6] + bias[6]; s1.w = acc[i][7] + bias[7];
        *(float4*)o = s0;
        *(float4*)(o + 4) = s1;
    }
}

// ---------------------------------------------------------------------------
// Kernel 2: cluster LSTM — weights in REGISTERS (packed f32x2), tx-mbarrier
// h-exchange. Re-tiled: thread = (4 rows x 32-k-chunk) -> 4x fewer h LDS.
// 128 CTAs = 16 clusters x 8. Cluster = (dir, batch-group of 8).
// CTA rank r owns h-cols [32r,32r+32) -> 128 gate rows.
// warp = k-chunk (8 chunks of 32 k); lane = row-group (4 rows each).
// ---------------------------------------------------------------------------
constexpr int LS_H  = 4096;                  // hs double buffer floats [2][8][256]
constexpr int LS_G  = 8192;                  // gs partials [8 kc][8 b][128 rows]
constexpr int LS_MBAR_OFF = (LS_H + LS_G) * 4;
constexpr int LSMEM_BYTES = LS_MBAR_OFF + 16;
constexpr unsigned TXBYTES = 2048u * 4u;     // per-phase expected bytes

#define MBWAIT_CL(mbar, par) do {                                              \
    asm volatile(                                                              \
        "{\n\t.reg .pred P1;\n\t"                                              \
        "WL%=:\n\t"                                                            \
        "mbarrier.try_wait.parity.acquire.cluster.shared::cta.b64 P1, [%0], %1, 0x989680;\n\t" \
        "@P1 bra WD%=;\n\t"                                                    \
        "bra WL%=;\n\t"                                                        \
        "WD%=:\n\t}"                                                           \
        :: "r"(mbar), "r"(par) : "memory");                                    \
} while (0)

__global__ void __launch_bounds__(256, 1) __cluster_dims__(8, 1, 1)
lstm_cluster_kernel(const float* __restrict__ w_hh_f, const float* __restrict__ w_hh_b)
{
    extern __shared__ __align__(16) float smem[];
    float* hs = smem;                  // [2][8 batches][256]
    float* gs = smem + LS_H;           // [8 kc][8 b][128 rows]

    const int tid = threadIdx.x;
    uint32_t rank;
    asm("mov.u32 %0, %%cluster_ctarank;" : "=r"(rank));
    const int cl = blockIdx.x >> 3;
    const int dir = cl & 1;
    const int bgrp = cl >> 1;

    const float* __restrict__ whh = dir ? w_hh_b : w_hh_f;

    // thread mapping: lane = row-group rg (rows 4rg..4rg+3), warp = k-chunk kc
    const int rg = tid & 31;
    const int kc = tid >> 5;

    // ---- weights into registers: 4 rows x 16 packed f32x2 (k in [32kc,32kc+32))
    unsigned long long w2[64];
#pragma unroll
    for (int r = 0; r < 4; ++r) {
        int rr = 4 * rg + r;
        int gg = (rr >> 5) * 256 + 32 * (int)rank + (rr & 31);
        const float* wsrc = whh + (size_t)gg * NH + kc * 32;
#pragma unroll
        for (int p = 0; p < 16; ++p)
            w2[r * 16 + p] = *(const unsigned long long*)(wsrc + 2 * p);
    }

    // SMEM u32 addresses
    uint32_t smem_base;
    asm("{ .reg .u64 t; cvta.to.shared.u64 t, %1; cvt.u32.u64 %0, t; }"
        : "=r"(smem_base) : "l"(smem));
    const uint32_t hs_sh = smem_base;
    const uint32_t mb_sh = smem_base + (uint32_t)LS_MBAR_OFF;

    if (tid == 0) {
        asm volatile("mbarrier.init.shared.b64 [%0], 1;" :: "r"(mb_sh) : "memory");
        asm volatile("mbarrier.init.shared.b64 [%0], 1;" :: "r"(mb_sh + 8) : "memory");
        asm volatile("mbarrier.arrive.expect_tx.shared.b64 _, [%0], %1;"
                     :: "r"(mb_sh), "r"(TXBYTES) : "memory");
        asm volatile("mbarrier.arrive.expect_tx.shared.b64 _, [%0], %1;"
                     :: "r"(mb_sh + 8), "r"(TXBYTES) : "memory");
    }
    __syncthreads();

    // cluster-wide: mbarrier inits visible before any st.async arrives
    asm volatile("barrier.cluster.arrive.aligned;" ::: "memory");
    asm volatile("barrier.cluster.wait.aligned;" ::: "memory");

    uint32_t rhs[8], rmb[8];
#pragma unroll
    for (int r = 0; r < 8; ++r) {
        asm("mapa.shared::cluster.u32 %0, %1, %2;" : "=r"(rhs[r]) : "r"(hs_sh), "r"(r));
        asm("mapa.shared::cluster.u32 %0, %1, %2;" : "=r"(rmb[r]) : "r"(mb_sh), "r"(r));
    }

    // activation mapping: batch ab = tid>>5, col aj = tid&31
    const int ab = tid >> 5, aj = tid & 31;
    float c_reg = 0.0f;
    float* ghout = g_h + ((size_t)(dir * NB + bgrp * 8 + ab)) * (NT * NH) + 32 * (int)rank + aj;
    const uint32_t h_off = (uint32_t)(ab * 256 + 32 * (int)rank + aj) * 4u;
    // gin for activation thread: 4 gate values per step
    const float* gact = g_gates + ((size_t)(dir * NB + bgrp * 8 + ab)) * NT * NG
                        + 32 * (int)rank + aj;

    int ph0 = 0, ph1 = 0;

    for (int t = 0; t < NT; ++t) {
        const int cur = t & 1, nxt = cur ^ 1;

        if (t > 0) {
            if (cur) { MBWAIT_CL(mb_sh + 8, ph1); ph1 ^= 1; }
            else     { MBWAIT_CL(mb_sh,     ph0); ph0 ^= 1; }
            if (tid == 0) {
                uint32_t mb = mb_sh + (uint32_t)(cur * 8);
                asm volatile("mbarrier.arrive.expect_tx.shared.b64 _, [%0], %1;"
                             :: "r"(mb), "r"(TXBYTES) : "memory");
            }
        }

        // prefetch this step's input-projection gate values (activation role)
        const float* gt = gact + (size_t)t * NG;
        float gi0 = gt[0];
        float gi1 = gt[256];
        float gi2 = gt[512];
        float gi3 = gt[768];

        if (t > 0) {
            // k-loop: per batch, 8 broadcast LDS.128 + 64 fma2 over 4 rows
#pragma unroll 2
            for (int b = 0; b < 8; ++b) {
                const ulonglong2* hb4 = (const ulonglong2*)(hs + cur * 2048 + b * 256 + kc * 32);
                unsigned long long a0 = 0ull, a1 = 0ull, a2 = 0ull, a3 = 0ull;
#pragma unroll
                for (int q = 0; q < 8; ++q) {
                    ulonglong2 hv = hb4[q];
                    fma2(a0, w2[0 * 16 + 2 * q], hv.x); fma2(a0, w2[0 * 16 + 2 * q + 1], hv.y);
                    fma2(a1, w2[1 * 16 + 2 * q], hv.x); fma2(a1, w2[1 * 16 + 2 * q + 1], hv.y);
                    fma2(a2, w2[2 * 16 + 2 * q], hv.x); fma2(a2, w2[2 * 16 + 2 * q + 1], hv.y);
                    fma2(a3, w2[3 * 16 + 2 * q], hv.x); fma2(a3, w2[3 * 16 + 2 * q + 1], hv.y);
                }
                float4 part;
                part.x = lo2(a0) + hi2(a0);
                part.y = lo2(a1) + hi2(a1);
                part.z = lo2(a2) + hi2(a2);
                part.w = lo2(a3) + hi2(a3);
                *(float4*)&gs[(kc * 8 + b) * 128 + 4 * rg] = part;
            }
        }
        __syncthreads();

        // activation (batch ab, col 32*rank+aj): reduce 8 k-chunk partials
        {
            float pi = gi0, pf = gi1, pg = gi2, po = gi3;
            if (t > 0) {
#pragma unroll
                for (int q = 0; q < 8; ++q) {
                    const float* gq = gs + (q * 8 + ab) * 128 + aj;
                    pi += gq[0];
                    pf += gq[32];
                    pg += gq[64];
                    po += gq[96];
                }
            }
            float iv = sigf(pi);
            float fv = sigf(pf);
            float gv = tanhf(pg);
            float ov = sigf(po);
            c_reg = fv * c_reg + iv * gv;
            float h = ov * tanhf(c_reg);
            ghout[(size_t)t * NH] = h;

            // pair adjacent cols -> b64 messages from even lanes (half count)
            float hn = __shfl_down_sync(0xffffffffu, h, 1);
            if ((aj & 1) == 0) {
                unsigned long long hp =
                    ((unsigned long long)__float_as_uint(hn) << 32) |
                    (unsigned long long)__float_as_uint(h);
                const uint32_t dsto = (uint32_t)(nxt * 2048 * 4) + h_off;
                const uint32_t mbo  = (uint32_t)(nxt * 8);
#pragma unroll
                for (int r = 0; r < 8; ++r) {
                    asm volatile(
                        "st.async.shared::cluster.mbarrier::complete_tx::bytes.b64 [%0], %1, [%2];"
                        :: "r"(rhs[r] + dsto), "l"(hp), "r"(rmb[r] + mbo) : "memory");
                }
            }
        }
        // no per-step cluster barrier: mbarrier tx-wait at next loop top
        // provides data-ready and anti-dependency ordering (proved R8/R9).
    }

    // drain final exchange so no CTA exits with in-flight st.async targeting it
    MBWAIT_CL(mb_sh, ph0);
    asm volatile("barrier.cluster.arrive.aligned;" ::: "memory");
    asm volatile("barrier.cluster.wait.aligned;" ::: "memory");
}

// ---------------------------------------------------------------------------
// Kernel 3: emissions. One warp per (b,t); lane = tag. 4 acc chains.
// ---------------------------------------------------------------------------
__global__ void __launch_bounds__(256) emissions_kernel(
    const int* __restrict__ lens, const float* __restrict__ b_out)
{
    const int item = blockIdx.x * 8 + (threadIdx.x >> 5);
    const int lane = threadIdx.x & 31;
    const int b = item >> 8, t = item & 255;
    const int len = lens[b];
    const int tb = (t < len) ? (len - 1 - t) : t;

    const float* hf = g_h + ((size_t)0 * NB + b) * NT * NH + (size_t)t * NH;
    const float* hb = g_h + ((size_t)1 * NB + b) * NT * NH + (size_t)tb * NH;
    const float* __restrict__ wT = g_wOutT;

    float acc0 = b_out[lane], acc1 = 0.f, acc2 = 0.f, acc3 = 0.f;
#pragma unroll 4
    for (int k16 = 0; k16 < 16; ++k16) {
        float4 ha = *(const float4*)(hf + k16 * 16);
        float4 hbv = *(const float4*)(hf + k16 * 16 + 4);
        float4 hc = *(const float4*)(hf + k16 * 16 + 8);
        float4 hd = *(const float4*)(hf + k16 * 16 + 12);
        const float* w0 = wT + (k16 * 16) * NC + lane;
        acc0 = fmaf(ha.x, w0[0 * NC], acc0);  acc1 = fmaf(ha.y, w0[1 * NC], acc1);
        acc2 = fmaf(ha.z, w0[2 * NC], acc2);  acc3 = fmaf(ha.w, w0[3 * NC], acc3);
        acc0 = fmaf(hbv.x, w0[4 * NC], acc0); acc1 = fmaf(hbv.y, w0[5 * NC], acc1);
        acc2 = fmaf(hbv.z, w0[6 * NC], acc2); acc3 = fmaf(hbv.w, w0[7 * NC], acc3);
        acc0 = fmaf(hc.x, w0[8 * NC], acc0);  acc1 = fmaf(hc.y, w0[9 * NC], acc1);
        acc2 = fmaf(hc.z, w0[10 * NC], acc2); acc3 = fmaf(hc.w, w0[11 * NC], acc3);
        acc0 = fmaf(hd.x, w0[12 * NC], acc0); acc1 = fmaf(hd.y, w0[13 * NC], acc1);
        acc2 = fmaf(hd.z, w0[14 * NC], acc2); acc3 = fmaf(hd.w, w0[15 * NC], acc3);
    }
#pragma unroll 4
    for (int k16 = 0; k16 < 16; ++k16) {
        float4 ha = *(const float4*)(hb + k16 * 16);
        float4 hbv = *(const float4*)(hb + k16 * 16 + 4);
        float4 hc = *(const float4*)(hb + k16 * 16 + 8);
        float4 hd = *(const float4*)(hb + k16 * 16 + 12);
        const float* w0 = wT + (NH + k16 * 16) * NC + lane;
        acc0 = fmaf(ha.x, w0[0 * NC], acc0);  acc1 = fmaf(ha.y, w0[1 * NC], acc1);
        acc2 = fmaf(ha.z, w0[2 * NC], acc2);  acc3 = fmaf(ha.w, w0[3 * NC], acc3);
        acc0 = fmaf(hbv.x, w0[4 * NC], acc0); acc1 = fmaf(hbv.y, w0[5 * NC], acc1);
        acc2 = fmaf(hbv.z, w0[6 * NC], acc2); acc3 = fmaf(hbv.w, w0[7 * NC], acc3);
        acc0 = fmaf(hc.x, w0[8 * NC], acc0);  acc1 = fmaf(hc.y, w0[9 * NC], acc1);
        acc2 = fmaf(hc.z, w0[10 * NC], acc2); acc3 = fmaf(hc.w, w0[11 * NC], acc3);
        acc0 = fmaf(hd.x, w0[12 * NC], acc0); acc1 = fmaf(hd.y, w0[13 * NC], acc1);
        acc2 = fmaf(hd.z, w0[14 * NC], acc2); acc3 = fmaf(hd.w, w0[15 * NC], acc3);
    }
    g_em[(size_t)item * NC + lane] = (acc0 + acc1) + (acc2 + acc3);
}

// ---------------------------------------------------------------------------
// Kernel 4: Viterbi decode. One warp per batch element; lane = tag.
// ---------------------------------------------------------------------------
__global__ void __launch_bounds__(32) viterbi_kernel(
    const int* __restrict__ lens,
    const float* __restrict__ start_trans, const float* __restrict__ end_trans,
    const float* __restrict__ trans, float* __restrict__ out)
{
    const int b = blockIdx.x;
    const int lane = threadIdx.x;

    __shared__ int hist[NT - 1][NC];

    float tr[NC];
#pragma unroll
    for (int cp = 0; cp < NC; ++cp) tr[cp] = trans[cp * NC + lane];

    const int len = lens[b];
    const float* emp = g_em + (size_t)b * NT * NC;
    float score = start_trans[lane] + emp[lane];
    float em_next = emp[NC + lane];

    for (int t = 1; t < NT; ++t) {
        float best = -1e30f;
        int bp = 0;
#pragma unroll
        for (int cp = 0; cp < NC; ++cp) {
            float sc = __shfl_sync(0xffffffffu, score, cp) + tr[cp];
            if (sc > best) { best = sc; bp = cp; }
        }
        hist[t - 1][lane] = bp;
        float em_cur = em_next;
        if (t + 1 < NT) em_next = emp[(t + 1) * NC + lane];
        if (t < len) score = best + em_cur;
    }
    score += end_trans[lane];

    float v = score;
    int idx = lane;
#pragma unroll
    for (int off = 16; off; off >>= 1) {
        float v2 = __shfl_xor_sync(0xffffffffu, v, off);
        int i2 = __shfl_xor_sync(0xffffffffu, idx, off);
        if (v2 > v || (v2 == v && i2 < idx)) { v = v2; idx = i2; }
    }

    if (lane == 0) {
        out[NB * NT + b] = v;
        int tag = idx;
        out[(size_t)b * NT + (NT - 1)] = (float)tag;
        for (int t = NT - 2; t >= 0; --t) {
            if (t < len - 1) tag = hist[t][tag];
            out[(size_t)b * NT + t] = (float)tag;
        }
    }
}

// ---------------------------------------------------------------------------
extern "C" void kernel_launch(void* const* d_in, const int* in_sizes, int n_in,
                              void* d_out, int out_size)
{
    const int*   sent   = (const int*)d_in[0];
    const int*   lens   = (const int*)d_in[1];
    const float* emb    = (const float*)d_in[2];
    const float* w_ih_f = (const float*)d_in[3];
    const float* w_hh_f = (const float*)d_in[4];
    const float* b_ih_f = (const float*)d_in[5];
    const float* b_hh_f = (const float*)d_in[6];
    const float* w_ih_b = (const float*)d_in[7];
    const float* w_hh_b = (const float*)d_in[8];
    const float* b_ih_b = (const float*)d_in[9];
    const float* b_hh_b = (const float*)d_in[10];
    const float* w_out  = (const float*)d_in[11];
    const float* b_out  = (const float*)d_in[12];
    const float* start_trans = (const float*)d_in[13];
    const float* end_trans   = (const float*)d_in[14];
    const float* trans       = (const float*)d_in[15];
    float* out = (float*)d_out;

    cudaFuncSetAttribute(lstm_cluster_kernel,
                         cudaFuncAttributeMaxDynamicSharedMemorySize, LSMEM_BYTES);

    dim3 tb(32, 8);
    transpose_wout_kernel<<<dim3((2 * NH) / 32, 1, 1), tb>>>(w_out);

    dim3 g1(128, 16);
    input_proj_kernel<<<g1, 256>>>(sent, lens, emb,
                                   w_ih_f, b_ih_f, b_hh_f,
                                   w_ih_b, b_ih_b, b_hh_b);
    lstm_cluster_kernel<<<128, 256, LSMEM_BYTES>>>(w_hh_f, w_hh_b);
    emissions_kernel<<<NB * NT / 8, 256>>>(lens, b_out);
    viterbi_kernel<<<NB, 32>>>(lens, start_trans, end_trans, trans, out);
}